// round 13
// baseline (speedup 1.0000x reference)
#include <cuda_runtime.h>
#include <cuda_fp16.h>
#include <cstdint>
#include <cstddef>

#define NMAX 200000
#define EMAX 600000
#define CH 128
#define LDP 136                      // padded row pitch in fp16 elems
#define EPITCH 24                    // eattr tile pitch (16 cols + pad)
#define PLANE_B (128 * LDP * 2)      // full 128-row plane bytes (W planes)
#define HPLANE_B (64 * LDP * 2)      // 64-row A/Z plane bytes
#define PLANE_F4 (PLANE_B / 16)      // 2176 float4 per full plane
#define FT_PITCH 132                 // fp32 staging pitch

// ---------------- scratch (device globals; no allocation allowed) ----------------
__device__ __half g_hh[(size_t)NMAX * CH];   // h hi plane (fp16)
__device__ __half g_hl[(size_t)NMAX * CH];   // h lo plane (fp16 residual)
__device__ int   g_src[EMAX];
__device__ int   g_dst[EMAX];
__device__ int2  g_epack[EMAX];              // (src, eid) in CSR order
__device__ __half g_msg[(size_t)EMAX * CH];  // CSR-ordered messages (per conv, reused)
__device__ int   g_cnt[NMAX];
__device__ int   g_off[NMAX + 1];
__device__ int   g_cur[NMAX];
__device__ int   g_bsum[256];
__device__ int   g_bbase[256];
__device__ int   g_idx64;
__device__ float4 g_wplanes[5 * PLANE_F4];   // 5 node-weights, fp16 planes [k][n]

// ---------------- init: zero counts + edge_index dtype sniff ----------------
__global__ void init_kernel(const unsigned* __restrict__ p, int nwords, int N)
{
    __shared__ unsigned s[32];
    int gi = blockIdx.x * 1024 + threadIdx.x;
    if (gi < N) g_cnt[gi] = 0;
    if (blockIdx.x == 0) {
        unsigned v = 0;
        for (int i = threadIdx.x; i < 4096; i += 1024) {
            int w = 2 * i + 1;
            if (w < nwords) v |= p[w];
        }
#pragma unroll
        for (int o = 16; o > 0; o >>= 1) v |= __shfl_xor_sync(0xffffffffu, v, o);
        int lane = threadIdx.x & 31, wid = threadIdx.x >> 5;
        if (lane == 0) s[wid] = v;
        __syncthreads();
        if (threadIdx.x == 0) {
            unsigned r = 0;
            for (int i = 0; i < 32; i++) r |= s[i];
            g_idx64 = (r == 0) ? 1 : 0;
        }
    }
}

// ---------------- weight prep ----------------
__global__ void prep_weights(const float* __restrict__ W0, const float* __restrict__ W1,
                             const float* __restrict__ W2, const float* __restrict__ W3,
                             const float* __restrict__ W4)
{
    int idx = blockIdx.x * blockDim.x + threadIdx.x;
    if (idx >= 5 * 128 * LDP) return;
    int wi = idx / (128 * LDP);
    int e  = idx % (128 * LDP);
    int k = e / LDP, n = e % LDP;
    const float* W = (wi == 0) ? W0 : (wi == 1) ? W1 : (wi == 2) ? W2 : (wi == 3) ? W3 : W4;
    __half h = __float2half_rn(0.f);
    if (n < 128) h = __float2half_rn(__ldg(W + k * 128 + n));
    ((__half*)g_wplanes)[(size_t)wi * 128 * LDP + e] = h;
}

// ---------------- CSR build ----------------
__global__ void convert_hist_kernel(const void* __restrict__ ei, int E)
{
    int i = blockIdx.x * blockDim.x + threadIdx.x;
    if (i >= E) return;
    int s, d;
    if (g_idx64) {
        const long long* p = (const long long*)ei;
        s = (int)p[i];
        d = (int)p[(size_t)E + i];
    } else {
        const int* p = (const int*)ei;
        s = p[i];
        d = p[E + i];
    }
    g_src[i] = s;
    g_dst[i] = d;
    atomicAdd(&g_cnt[d], 1);
}

__global__ void scan1_kernel(int N)
{
    __shared__ int s[32];
    int idx = blockIdx.x * 1024 + threadIdx.x;
    int v = (idx < N) ? g_cnt[idx] : 0;
    int t = v;
#pragma unroll
    for (int o = 16; o > 0; o >>= 1) t += __shfl_xor_sync(0xffffffffu, t, o);
    if ((threadIdx.x & 31) == 0) s[threadIdx.x >> 5] = t;
    __syncthreads();
    if (threadIdx.x == 0) {
        int r = 0;
        for (int i = 0; i < 32; i++) r += s[i];
        g_bsum[blockIdx.x] = r;
    }
}

__global__ void scan2_kernel(int nb, int N, int E)
{
    __shared__ int s[256];
    int t = threadIdx.x;
    int v = (t < nb) ? g_bsum[t] : 0;
    s[t] = v;
    __syncthreads();
#pragma unroll
    for (int o = 1; o < 256; o <<= 1) {
        int nv = s[t];
        if (t >= o) nv += s[t - o];
        __syncthreads();
        s[t] = nv;
        __syncthreads();
    }
    if (t < nb) g_bbase[t] = s[t] - v;
    if (t == 0) g_off[N] = E;
}

__global__ void scan3_kernel(int N)
{
    __shared__ int s[1024];
    int idx = blockIdx.x * 1024 + threadIdx.x;
    int t = threadIdx.x;
    int v = (idx < N) ? g_cnt[idx] : 0;
    s[t] = v;
    __syncthreads();
#pragma unroll
    for (int o = 1; o < 1024; o <<= 1) {
        int nv = s[t];
        if (t >= o) nv += s[t - o];
        __syncthreads();
        s[t] = nv;
        __syncthreads();
    }
    if (idx < N) {
        int excl = g_bbase[blockIdx.x] + s[t] - v;
        g_off[idx] = excl;
        g_cur[idx] = excl;
    }
}

__global__ void place_kernel(int E)
{
    int i = blockIdx.x * blockDim.x + threadIdx.x;
    if (i >= E) return;
    int d = g_dst[i];
    int p = atomicAdd(&g_cur[d], 1);
    g_epack[p] = make_int2(g_src[i], i);
}

// ---------------- fp16 helpers ----------------
__device__ __forceinline__ uint32_t pack_h2_hi(float a, float b)
{
    __half ha = __float2half_rn(a), hb = __float2half_rn(b);
    return ((uint32_t)__half_as_ushort(hb) << 16) | __half_as_ushort(ha);
}
__device__ __forceinline__ uint32_t pack_h2_lo(float a, float b)
{
    __half ha = __float2half_rn(a), hb = __float2half_rn(b);
    __half la = __float2half_rn(a - __half2float(ha));
    __half lb = __float2half_rn(b - __half2float(hb));
    return ((uint32_t)__half_as_ushort(lb) << 16) | __half_as_ushort(la);
}
__device__ __forceinline__ void ldsm_x4(uint32_t* r, const void* p)
{
    uint32_t a = (uint32_t)__cvta_generic_to_shared(p);
    asm volatile("ldmatrix.sync.aligned.m8n8.x4.shared.b16 {%0,%1,%2,%3}, [%4];"
                 : "=r"(r[0]), "=r"(r[1]), "=r"(r[2]), "=r"(r[3]) : "r"(a));
}
__device__ __forceinline__ void ldsm_x4_t(uint32_t* r, const void* p)
{
    uint32_t a = (uint32_t)__cvta_generic_to_shared(p);
    asm volatile("ldmatrix.sync.aligned.m8n8.x4.trans.shared.b16 {%0,%1,%2,%3}, [%4];"
                 : "=r"(r[0]), "=r"(r[1]), "=r"(r[2]), "=r"(r[3]) : "r"(a));
}
__device__ __forceinline__ void mma_f16(float* c, const uint32_t* a, uint32_t b0, uint32_t b1)
{
    asm volatile("mma.sync.aligned.m16n8k16.row.col.f32.f16.f16.f32 "
                 "{%0,%1,%2,%3}, {%4,%5,%6,%7}, {%8,%9}, {%0,%1,%2,%3};"
                 : "+f"(c[0]), "+f"(c[1]), "+f"(c[2]), "+f"(c[3])
                 : "r"(a[0]), "r"(a[1]), "r"(a[2]), "r"(a[3]), "r"(b0), "r"(b1));
}
__device__ __forceinline__ void cp16(uint32_t dst, const void* src)
{
    asm volatile("cp.async.cg.shared.global [%0], [%1], 16;" :: "r"(dst), "l"(src) : "memory");
}
__device__ __forceinline__ void cp_commit_wait()
{
    asm volatile("cp.async.commit_group;\ncp.async.wait_group 0;" ::: "memory");
}

// ---------------- message GEMM: msg[p] = relu(hh[src(p)] + eattr[eid(p)]@We + be) ----------------
#define MG_HS   (128 * LDP * 2)
#define MG_AE   (MG_HS + 2 * 128 * EPITCH * 2)
#define MG_W    (MG_AE + 2 * 16 * LDP * 2)
#define MG_SMEM (MG_W + 512 + 256)

__global__ __launch_bounds__(256, 3)
void msggemm_kernel(const float* __restrict__ eattr,
                    const float* __restrict__ We, const float* __restrict__ be,
                    const __half* __restrict__ hh, __half* __restrict__ msg, int E)
{
    extern __shared__ char sm[];
    __half* Hs  = (__half*)sm;                   // [128][LDP]
    __half* Aeh = (__half*)(sm + MG_HS);         // [128][EPITCH]
    __half* Ael = Aeh + 128 * EPITCH;
    __half* Wh  = (__half*)(sm + MG_AE);         // [16][LDP]
    __half* Wl  = Wh + 16 * LDP;
    float* sb   = (float*)(sm + MG_W);
    uint32_t sbH = (uint32_t)__cvta_generic_to_shared(Hs);

    const int tid = threadIdx.x;
    const int warp = tid >> 5, lane = tid & 31;
    const int p0 = blockIdx.x * 128;

#pragma unroll
    for (int i = 0; i < 8; i++) {
        int j = tid + i * 256;
        int rowp = j >> 4, c = j & 15;
        int p = p0 + rowp;
        int s = (p < E) ? __ldg(&g_epack[p]).x : 0;
        cp16(sbH + rowp * (LDP * 2) + c * 16, (const char*)(hh + (size_t)s * CH) + c * 16);
    }

    for (int i = tid; i < 2048; i += 256) {
        int k = i >> 7, n = i & 127;
        float v = __ldg(We + i);
        __half h = __float2half_rn(v);
        Wh[k * LDP + n] = h;
        Wl[k * LDP + n] = __float2half_rn(v - __half2float(h));
    }
    if (tid < 128) sb[tid] = __ldg(be + tid);

    {
        int rowp = tid >> 1;
        int hoff = (tid & 1) * 8;
        int p = p0 + rowp;
        float4 v0 = make_float4(0.f, 0.f, 0.f, 0.f), v1 = v0;
        if (p < E) {
            int eid = __ldg(&g_epack[p]).y;
            const float4* ea = (const float4*)eattr + (size_t)eid * 4 + (tid & 1) * 2;
            v0 = __ldg(ea);
            v1 = __ldg(ea + 1);
        }
        *(uint2*)(Aeh + rowp * EPITCH + hoff)     = make_uint2(pack_h2_hi(v0.x, v0.y), pack_h2_hi(v0.z, v0.w));
        *(uint2*)(Aeh + rowp * EPITCH + hoff + 4) = make_uint2(pack_h2_hi(v1.x, v1.y), pack_h2_hi(v1.z, v1.w));
        *(uint2*)(Ael + rowp * EPITCH + hoff)     = make_uint2(pack_h2_lo(v0.x, v0.y), pack_h2_lo(v0.z, v0.w));
        *(uint2*)(Ael + rowp * EPITCH + hoff + 4) = make_uint2(pack_h2_lo(v1.x, v1.y), pack_h2_lo(v1.z, v1.w));
    }
    cp_commit_wait();
    __syncthreads();

    const int wr0 = warp * 16;
    const int arow = wr0 + (lane & 15);
    const int aoff = (lane >> 4) << 3;

    uint32_t ah[4], al[4];
    ldsm_x4(ah, Aeh + arow * EPITCH + aoff);
    ldsm_x4(al, Ael + arow * EPITCH + aoff);

    const int brow = (lane & 15);
    const int cb = (lane & 3) * 2;
    const int rl0 = wr0 + (lane >> 2);
    const int r0 = p0 + rl0;

#pragma unroll
    for (int nh = 0; nh < 2; nh++) {
        float acc[8][4];
#pragma unroll
        for (int t = 0; t < 8; t++)
#pragma unroll
            for (int j = 0; j < 4; j++) acc[t][j] = 0.f;
#pragma unroll
        for (int ng = 0; ng < 4; ng++) {
            const int n0 = nh * 64 + ng * 16;
            uint32_t bh[4], bl[4];
            ldsm_x4_t(bh, Wh + brow * LDP + n0 + aoff);
            ldsm_x4_t(bl, Wl + brow * LDP + n0 + aoff);
            mma_f16(acc[ng * 2],     ah, bh[0], bh[1]);
            mma_f16(acc[ng * 2],     al, bh[0], bh[1]);
            mma_f16(acc[ng * 2],     ah, bl[0], bl[1]);
            mma_f16(acc[ng * 2 + 1], ah, bh[2], bh[3]);
            mma_f16(acc[ng * 2 + 1], al, bh[2], bh[3]);
            mma_f16(acc[ng * 2 + 1], ah, bl[2], bl[3]);
        }
#pragma unroll
        for (int t = 0; t < 8; t++) {
            const int n = nh * 64 + t * 8 + cb;
            const float b0 = sb[n], b1 = sb[n + 1];
            {
                float2 hv = __half22float2(*(__half2*)(Hs + (size_t)rl0 * LDP + n));
                float m0 = fmaxf(hv.x + acc[t][0] + b0, 0.f);
                float m1 = fmaxf(hv.y + acc[t][1] + b1, 0.f);
                if (r0 < E)
                    *(uint32_t*)(msg + (size_t)r0 * CH + n) = pack_h2_hi(m0, m1);
            }
            {
                float2 hv = __half22float2(*(__half2*)(Hs + (size_t)(rl0 + 8) * LDP + n));
                float m0 = fmaxf(hv.x + acc[t][2] + b0, 0.f);
                float m1 = fmaxf(hv.y + acc[t][3] + b1, 0.f);
                if (r0 + 8 < E)
                    *(uint32_t*)(msg + (size_t)(r0 + 8) * CH + n) = pack_h2_hi(m0, m1);
            }
        }
    }
}

// stage 64-row A tile (fp32 source) into fp16 hi/lo planes
__device__ __forceinline__ void stage_a_f16_64(const float* __restrict__ A,
                                               __half* Ah, __half* Al,
                                               int tid, int row0, int M)
{
#pragma unroll
    for (int i = 0; i < 8; i++) {
        int idx = tid + i * 256;
        int r = idx >> 5, c4 = idx & 31;
        int g = row0 + r;
        float4 v = make_float4(0.f, 0.f, 0.f, 0.f);
        if (g < M) v = __ldg((const float4*)(A + (size_t)g * CH) + c4);
        *(uint2*)(Ah + r * LDP + c4 * 4) = make_uint2(pack_h2_hi(v.x, v.y), pack_h2_hi(v.z, v.w));
        *(uint2*)(Al + r * LDP + c4 * 4) = make_uint2(pack_h2_lo(v.x, v.y), pack_h2_lo(v.z, v.w));
    }
}

// 2-term fp16 pass, warp tile 16 rows x 64 cols
__device__ __forceinline__ void mma_pass16(const __half* Ah, const __half* Al,
                                           const __half* Bh,
                                           int lane, int wr0, int wc0, float acc[8][4])
{
#pragma unroll
    for (int t = 0; t < 8; t++)
#pragma unroll
        for (int j = 0; j < 4; j++) acc[t][j] = 0.f;

    const int arow = wr0 + (lane & 15);
    const int aoff = (lane >> 4) << 3;

#pragma unroll
    for (int kc = 0; kc < 8; kc++) {
        const int kb = kc * 16;
        uint32_t ah[4], al[4];
        ldsm_x4(ah, Ah + (size_t)arow * LDP + kb + aoff);
        ldsm_x4(al, Al + (size_t)arow * LDP + kb + aoff);
        const int brow = kb + (lane & 15);
#pragma unroll
        for (int ng = 0; ng < 4; ng++) {
            uint32_t b[4];
            ldsm_x4_t(b, Bh + (size_t)brow * LDP + wc0 + ng * 16 + aoff);
            mma_f16(acc[ng * 2],     ah, b[0], b[1]);
            mma_f16(acc[ng * 2],     al, b[0], b[1]);
            mma_f16(acc[ng * 2 + 1], ah, b[2], b[3]);
            mma_f16(acc[ng * 2 + 1], al, b[2], b[3]);
        }
    }
}

// write z=relu(acc+bias) split hi/lo into 64-row smem planes
__device__ __forceinline__ void z_to_planes16(__half* Ah, __half* Al, const float* sb,
                                              float acc[8][4], int lane, int wr0, int wc0)
{
    const int cb = (lane & 3) * 2;
    const int rl = wr0 + (lane >> 2);
#pragma unroll
    for (int t = 0; t < 8; t++) {
        const int n = wc0 + t * 8 + cb;
        const float b0 = sb[n], b1v = sb[n + 1];
        float z0 = fmaxf(acc[t][0] + b0, 0.f);
        float z1 = fmaxf(acc[t][1] + b1v, 0.f);
        float z2 = fmaxf(acc[t][2] + b0, 0.f);
        float z3 = fmaxf(acc[t][3] + b1v, 0.f);
        *(uint32_t*)(Ah + (size_t)rl * LDP + n)       = pack_h2_hi(z0, z1);
        *(uint32_t*)(Al + (size_t)rl * LDP + n)       = pack_h2_lo(z0, z1);
        *(uint32_t*)(Ah + (size_t)(rl + 8) * LDP + n) = pack_h2_hi(z2, z3);
        *(uint32_t*)(Al + (size_t)(rl + 8) * LDP + n) = pack_h2_lo(z2, z3);
    }
}

// coalesced copy of both 64-row smem planes to global fp16 arrays
__device__ __forceinline__ void planes_to_global64(const __half* Ah, const __half* Al,
                                                   __half* oh, __half* ol,
                                                   int tid, int row0, int M)
{
#pragma unroll
    for (int i = 0; i < 4; i++) {
        int j = tid + i * 256;
        int r = j >> 4, c = j & 15;
        int g = row0 + r;
        if (g < M) {
            uint4 vh = *(const uint4*)((const char*)Ah + (size_t)r * LDP * 2 + c * 16);
            uint4 vl = *(const uint4*)((const char*)Al + (size_t)r * LDP * 2 + c * 16);
            *(uint4*)((char*)(oh + (size_t)g * CH) + c * 16) = vh;
            *(uint4*)((char*)(ol + (size_t)g * CH) + c * 16) = vl;
        }
    }
}

// ---------------- encoder GEMM (64-row tile, occ 3) ----------------
#define G1_SMEM (2 * HPLANE_B + PLANE_B + 512)

__global__ __launch_bounds__(256, 3)
void gemm_tc(const float* __restrict__ A, const float4* __restrict__ WhP,
             const float* __restrict__ bias,
             __half* __restrict__ oh, __half* __restrict__ ol, int M)
{
    extern __shared__ char sm[];
    __half* Ah = (__half*)sm;
    __half* Al = Ah + 64 * LDP;
    __half* Wh = Al + 64 * LDP;
    float* sbias = (float*)(sm + 2 * HPLANE_B + PLANE_B);
    uint32_t sbW = (uint32_t)__cvta_generic_to_shared(Wh);

    const int tid = threadIdx.x;
    const int warp = tid >> 5, lane = tid & 31;
    const int row0 = blockIdx.x * 64;

#pragma unroll
    for (int i = 0; i < 9; i++) {
        int j = tid + i * 256;
        if (j < PLANE_F4) cp16(sbW + j * 16, WhP + j);
    }
    if (tid < 128) sbias[tid] = __ldg(bias + tid);

    stage_a_f16_64(A, Ah, Al, tid, row0, M);
    cp_commit_wait();
    __syncthreads();

    const int wr0 = (warp >> 1) * 16;
    const int wc0 = (warp & 1) * 64;

    float acc[8][4];
    mma_pass16(Ah, Al, Wh, lane, wr0, wc0, acc);
    __syncthreads();

    z_to_planes16(Ah, Al, sbias, acc, lane, wr0, wc0);
    __syncthreads();
    planes_to_global64(Ah, Al, oh, ol, tid, row0, M);
}

// ---------------- fused conv MLP: aggregate (sequential msg) + 2-layer MLP ----------------
// z[n] = (1+eps)*(hh[n]+hl[n]) + sum_{p in [off[n],off[n+1])} msg[p]   (built in smem)
// out  = relu(relu(z@W1+b1)@W2+b2)
#define G2_SMEM (2 * HPLANE_B + PLANE_B + 1024)

template <bool OUT16>
__global__ __launch_bounds__(256, 3)
void gemm2_tc(const __half* __restrict__ hh, const __half* __restrict__ hl,
              const __half* __restrict__ msg, const float* __restrict__ epsp,
              const float4* __restrict__ W1P, const float4* __restrict__ W2P,
              const float* __restrict__ b1, const float* __restrict__ b2,
              float* __restrict__ out, __half* __restrict__ oh, __half* __restrict__ ol,
              int M)
{
    extern __shared__ char sm[];
    __half* Ah = (__half*)sm;
    __half* Al = Ah + 64 * LDP;
    __half* Wp = Al + 64 * LDP;
    float* sb1 = (float*)(sm + 2 * HPLANE_B + PLANE_B);
    float* sb2 = sb1 + 128;
    uint32_t sbW = (uint32_t)__cvta_generic_to_shared(Wp);

    const int tid = threadIdx.x;
    const int warp = tid >> 5, lane = tid & 31;
    const int row0 = blockIdx.x * 64;

#pragma unroll
    for (int i = 0; i < 9; i++) {
        int j = tid + i * 256;
        if (j < PLANE_F4) cp16(sbW + j * 16, W1P + j);
    }
    if (tid < 128) sb1[tid] = __ldg(b1 + tid);
    else           sb2[tid - 128] = __ldg(b2 + tid - 128);

    const float epc = 1.0f + __ldg(epsp);

    // ---- aggregation: warp w handles local rows [w*8, w*8+8); lane owns 4 channels ----
#pragma unroll
    for (int i = 0; i < 8; i++) {
        const int rl = warp * 8 + i;
        const int n = row0 + rl;
        float4 acc = make_float4(0.f, 0.f, 0.f, 0.f);
        if (n < M) {
            uint2 uh = __ldg((const uint2*)(hh + (size_t)n * CH) + lane);
            uint2 ul = __ldg((const uint2*)(hl + (size_t)n * CH) + lane);
            float2 h01 = __half22float2(*(__half2*)&uh.x);
            float2 h23 = __half22float2(*(__half2*)&uh.y);
            float2 l01 = __half22float2(*(__half2*)&ul.x);
            float2 l23 = __half22float2(*(__half2*)&ul.y);
            acc.x = epc * (h01.x + l01.x);
            acc.y = epc * (h01.y + l01.y);
            acc.z = epc * (h23.x + l23.x);
            acc.w = epc * (h23.y + l23.y);

            const int p0 = __ldg(&g_off[n]);
            const int p1 = __ldg(&g_off[n + 1]);
            uint2 euA = make_uint2(0, 0), euB = euA;
            if (p0 < p1)     euA = __ldg((const uint2*)(msg + (size_t)p0 * CH) + lane);
            if (p0 + 1 < p1) euB = __ldg((const uint2*)(msg + (size_t)(p0 + 1) * CH) + lane);
            for (int p = p0; p < p1; ++p) {
                uint2 ce = euA;
                euA = euB;
                if (p + 2 < p1) euB = __ldg((const uint2*)(msg + (size_t)(p + 2) * CH) + lane);
                float2 f01 = __half22float2(*(__half2*)&ce.x);
                float2 f23 = __half22float2(*(__half2*)&ce.y);
                acc.x += f01.x;
                acc.y += f01.y;
                acc.z += f23.x;
                acc.w += f23.y;
            }
        }
        *(uint2*)(Ah + (size_t)rl * LDP + lane * 4) =
            make_uint2(pack_h2_hi(acc.x, acc.y), pack_h2_hi(acc.z, acc.w));
        *(uint2*)(Al + (size_t)rl * LDP + lane * 4) =
            make_uint2(pack_h2_lo(acc.x, acc.y), pack_h2_lo(acc.z, acc.w));
    }
    cp_commit_wait();
    __syncthreads();

    const int wr0 = (warp >> 1) * 16;
    const int wc0 = (warp & 1) * 64;

    // ---- layer 1 ----
    float acc[8][4];
    mma_pass16(Ah, Al, Wp, lane, wr0, wc0, acc);
    __syncthreads();

#pragma unroll
    for (int i = 0; i < 9; i++) {
        int j = tid + i * 256;
        if (j < PLANE_F4) cp16(sbW + j * 16, W2P + j);
    }
    z_to_planes16(Ah, Al, sb1, acc, lane, wr0, wc0);
    cp_commit_wait();
    __syncthreads();

    // ---- layer 2 ----
    mma_pass16(Ah, Al, Wp, lane, wr0, wc0, acc);
    __syncthreads();

    if (OUT16) {
        z_to_planes16(Ah, Al, sb2, acc, lane, wr0, wc0);
        __syncthreads();
        planes_to_global64(Ah, Al, oh, ol, tid, row0, M);
    } else {
        float* ftile = (float*)sm;
        const int cb = (lane & 3) * 2;
        const int rl = wr0 + (lane >> 2);
#pragma unroll
        for (int t = 0; t < 8; t++) {
            const int n = wc0 + t * 8 + cb;
            const float b0 = sb2[n], b1v = sb2[n + 1];
            float2 o0 = make_float2(fmaxf(acc[t][0] + b0, 0.f),
                                    fmaxf(acc[t][1] + b1v, 0.f));
            float2 o1 = make_float2(fmaxf(acc[t][2] + b0, 0.f),
                                    fmaxf(acc[t][3] + b1v, 0.f));
            *(float2*)(ftile + (size_t)rl * FT_PITCH + n)       = o0;
            *(float2*)(ftile + (size_t)(rl + 8) * FT_PITCH + n) = o1;
        }
        __syncthreads();
#pragma unroll
        for (int i = 0; i < 8; i++) {
            int j = tid + i * 256;
            int r = j >> 5, c = j & 31;
            int g = row0 + r;
            if (g < M) {
                float4 v = *(const float4*)(ftile + (size_t)r * FT_PITCH + c * 4);
                *(float4*)(out + (size_t)g * CH + c * 4) = v;
            }
        }
    }
}

// ---------------- launch ----------------
extern "C" void kernel_launch(void* const* d_in, const int* in_sizes, int n_in,
                              void* d_out, int out_size)
{
    const float* x     = (const float*)d_in[0];
    const void*  eidx  = d_in[1];
    const float* eattr = (const float*)d_in[2];
    const float* W_enc = (const float*)d_in[3];
    const float* b_enc = (const float*)d_in[4];
    const float* We1   = (const float*)d_in[5];
    const float* be1   = (const float*)d_in[6];
    const float* W11   = (const float*)d_in[7];
    const float* b11   = (const float*)d_in[8];
    const float* W12   = (const float*)d_in[9];
    const float* b12   = (const float*)d_in[10];
    const float* eps1  = (const float*)d_in[11];
    const float* We2   = (const float*)d_in[12];
    const float* be2   = (const float*)d_in[13];
    const float* W21   = (const float*)d_in[14];
    const float* b21   = (const float*)d_in[15];
    const float* W22   = (const float*)d_in[16];
    const float* b22   = (const float*)d_in[17];
    const float* eps2  = (const float*)d_in[18];

    const int N = in_sizes[0] / CH;
    const int E = in_sizes[2] / 16;
    float* out = (float*)d_out;

    float4* wpl;
    __half *msgP, *hhP, *hlP;
    cudaGetSymbolAddress((void**)&wpl, g_wplanes);
    cudaGetSymbolAddress((void**)&msgP, g_msg);
    cudaGetSymbolAddress((void**)&hhP, g_hh);
    cudaGetSymbolAddress((void**)&hlP, g_hl);

    cudaFuncSetAttribute((const void*)gemm_tc,
                         cudaFuncAttributeMaxDynamicSharedMemorySize, G1_SMEM);
    cudaFuncSetAttribute((const void*)gemm2_tc<true>,
                         cudaFuncAttributeMaxDynamicSharedMemorySize, G2_SMEM);
    cudaFuncSetAttribute((const void*)gemm2_tc<false>,
                         cudaFuncAttributeMaxDynamicSharedMemorySize, G2_SMEM);
    cudaFuncSetAttribute((const void*)msggemm_kernel,
                         cudaFuncAttributeMaxDynamicSharedMemorySize, MG_SMEM);

    const int nb = (N + 1023) / 1024;
    const int gb = (N + 63) / 64;
    const int ge = (E + 127) / 128;

    init_kernel<<<nb, 1024>>>((const unsigned*)eidx, 2 * E, N);
    prep_weights<<<(5 * 128 * LDP + 255) / 256, 256>>>(W_enc, W11, W12, W21, W22);
    gemm_tc<<<gb, 256, G1_SMEM>>>(x, wpl, b_enc, hhP, hlP, N);
    convert_hist_kernel<<<(E + 255) / 256, 256>>>(eidx, E);
    scan1_kernel<<<nb, 1024>>>(N);
    scan2_kernel<<<1, 256>>>(nb, N, E);
    scan3_kernel<<<nb, 1024>>>(N);
    place_kernel<<<(E + 255) / 256, 256>>>(E);

    // ---- conv1 ----
    msggemm_kernel<<<ge, 256, MG_SMEM>>>(eattr, We1, be1, hhP, msgP, E);
    gemm2_tc<true><<<gb, 256, G2_SMEM>>>(hhP, hlP, msgP, eps1,
                                         wpl + 1 * PLANE_F4, wpl + 2 * PLANE_F4,
                                         b11, b12, nullptr, hhP, hlP, N);

    // ---- conv2 ----
    msggemm_kernel<<<ge, 256, MG_SMEM>>>(eattr, We2, be2, hhP, msgP, E);
    gemm2_tc<false><<<gb, 256, G2_SMEM>>>(hhP, hlP, msgP, eps2,
                                          wpl + 3 * PLANE_F4, wpl + 4 * PLANE_F4,
                                          b21, b22, out, nullptr, nullptr, N);
}

// round 14
// speedup vs baseline: 1.1009x; 1.1009x over previous
#include <cuda_runtime.h>
#include <cuda_fp16.h>
#include <cstdint>
#include <cstddef>

#define NMAX 200000
#define EMAX 600000
#define CH 128
#define LDP 136                      // padded row pitch in fp16 elems
#define EPITCH 24                    // eattr tile pitch (16 cols + pad)
#define PLANE_B (128 * LDP * 2)      // full 128-row plane bytes (W planes)
#define HPLANE_B (64 * LDP * 2)      // 64-row A/Z plane bytes
#define PLANE_F4 (PLANE_B / 16)      // 2176 float4 per full plane
#define FT_PITCH 132                 // fp32 staging pitch

// ---------------- scratch (device globals; no allocation allowed) ----------------
__device__ __half g_hh[(size_t)NMAX * CH];   // h hi plane (fp16)
__device__ __half g_hl[(size_t)NMAX * CH];   // h lo plane (fp16 residual)
__device__ float g_agg[(size_t)NMAX * CH];
__device__ int   g_src[EMAX];
__device__ int   g_dst[EMAX];
__device__ int2  g_epack[EMAX];              // (src, eid) in CSR order
__device__ __half g_msg[(size_t)EMAX * CH];  // CSR-ordered messages (per conv, reused)
__device__ int   g_cnt[NMAX];
__device__ int   g_off[NMAX + 1];
__device__ int   g_cur[NMAX];
__device__ int   g_bsum[256];
__device__ int   g_bbase[256];
__device__ int   g_idx64;
__device__ float4 g_wplanes[5 * PLANE_F4];   // 5 node-weights, fp16 planes [k][n]

// ---------------- init: zero counts + edge_index dtype sniff ----------------
__global__ void init_kernel(const unsigned* __restrict__ p, int nwords, int N)
{
    __shared__ unsigned s[32];
    int gi = blockIdx.x * 1024 + threadIdx.x;
    if (gi < N) g_cnt[gi] = 0;
    if (blockIdx.x == 0) {
        unsigned v = 0;
        for (int i = threadIdx.x; i < 4096; i += 1024) {
            int w = 2 * i + 1;
            if (w < nwords) v |= p[w];
        }
#pragma unroll
        for (int o = 16; o > 0; o >>= 1) v |= __shfl_xor_sync(0xffffffffu, v, o);
        int lane = threadIdx.x & 31, wid = threadIdx.x >> 5;
        if (lane == 0) s[wid] = v;
        __syncthreads();
        if (threadIdx.x == 0) {
            unsigned r = 0;
            for (int i = 0; i < 32; i++) r |= s[i];
            g_idx64 = (r == 0) ? 1 : 0;
        }
    }
}

// ---------------- weight prep ----------------
__global__ void prep_weights(const float* __restrict__ W0, const float* __restrict__ W1,
                             const float* __restrict__ W2, const float* __restrict__ W3,
                             const float* __restrict__ W4)
{
    int idx = blockIdx.x * blockDim.x + threadIdx.x;
    if (idx >= 5 * 128 * LDP) return;
    int wi = idx / (128 * LDP);
    int e  = idx % (128 * LDP);
    int k = e / LDP, n = e % LDP;
    const float* W = (wi == 0) ? W0 : (wi == 1) ? W1 : (wi == 2) ? W2 : (wi == 3) ? W3 : W4;
    __half h = __float2half_rn(0.f);
    if (n < 128) h = __float2half_rn(__ldg(W + k * 128 + n));
    ((__half*)g_wplanes)[(size_t)wi * 128 * LDP + e] = h;
}

// ---------------- CSR build ----------------
__global__ void convert_hist_kernel(const void* __restrict__ ei, int E)
{
    int i = blockIdx.x * blockDim.x + threadIdx.x;
    if (i >= E) return;
    int s, d;
    if (g_idx64) {
        const long long* p = (const long long*)ei;
        s = (int)p[i];
        d = (int)p[(size_t)E + i];
    } else {
        const int* p = (const int*)ei;
        s = p[i];
        d = p[E + i];
    }
    g_src[i] = s;
    g_dst[i] = d;
    atomicAdd(&g_cnt[d], 1);
}

__global__ void scan1_kernel(int N)
{
    __shared__ int s[32];
    int idx = blockIdx.x * 1024 + threadIdx.x;
    int v = (idx < N) ? g_cnt[idx] : 0;
    int t = v;
#pragma unroll
    for (int o = 16; o > 0; o >>= 1) t += __shfl_xor_sync(0xffffffffu, t, o);
    if ((threadIdx.x & 31) == 0) s[threadIdx.x >> 5] = t;
    __syncthreads();
    if (threadIdx.x == 0) {
        int r = 0;
        for (int i = 0; i < 32; i++) r += s[i];
        g_bsum[blockIdx.x] = r;
    }
}

__global__ void scan2_kernel(int nb, int N, int E)
{
    __shared__ int s[256];
    int t = threadIdx.x;
    int v = (t < nb) ? g_bsum[t] : 0;
    s[t] = v;
    __syncthreads();
#pragma unroll
    for (int o = 1; o < 256; o <<= 1) {
        int nv = s[t];
        if (t >= o) nv += s[t - o];
        __syncthreads();
        s[t] = nv;
        __syncthreads();
    }
    if (t < nb) g_bbase[t] = s[t] - v;
    if (t == 0) g_off[N] = E;
}

__global__ void scan3_kernel(int N)
{
    __shared__ int s[1024];
    int idx = blockIdx.x * 1024 + threadIdx.x;
    int t = threadIdx.x;
    int v = (idx < N) ? g_cnt[idx] : 0;
    s[t] = v;
    __syncthreads();
#pragma unroll
    for (int o = 1; o < 1024; o <<= 1) {
        int nv = s[t];
        if (t >= o) nv += s[t - o];
        __syncthreads();
        s[t] = nv;
        __syncthreads();
    }
    if (idx < N) {
        int excl = g_bbase[blockIdx.x] + s[t] - v;
        g_off[idx] = excl;
        g_cur[idx] = excl;
    }
}

__global__ void place_kernel(int E)
{
    int i = blockIdx.x * blockDim.x + threadIdx.x;
    if (i >= E) return;
    int d = g_dst[i];
    int p = atomicAdd(&g_cur[d], 1);
    g_epack[p] = make_int2(g_src[i], i);
}

// ---------------- fp16 helpers ----------------
__device__ __forceinline__ uint32_t pack_h2_hi(float a, float b)
{
    __half ha = __float2half_rn(a), hb = __float2half_rn(b);
    return ((uint32_t)__half_as_ushort(hb) << 16) | __half_as_ushort(ha);
}
__device__ __forceinline__ uint32_t pack_h2_lo(float a, float b)
{
    __half ha = __float2half_rn(a), hb = __float2half_rn(b);
    __half la = __float2half_rn(a - __half2float(ha));
    __half lb = __float2half_rn(b - __half2float(hb));
    return ((uint32_t)__half_as_ushort(lb) << 16) | __half_as_ushort(la);
}
__device__ __forceinline__ void ldsm_x4(uint32_t* r, const void* p)
{
    uint32_t a = (uint32_t)__cvta_generic_to_shared(p);
    asm volatile("ldmatrix.sync.aligned.m8n8.x4.shared.b16 {%0,%1,%2,%3}, [%4];"
                 : "=r"(r[0]), "=r"(r[1]), "=r"(r[2]), "=r"(r[3]) : "r"(a));
}
__device__ __forceinline__ void ldsm_x4_t(uint32_t* r, const void* p)
{
    uint32_t a = (uint32_t)__cvta_generic_to_shared(p);
    asm volatile("ldmatrix.sync.aligned.m8n8.x4.trans.shared.b16 {%0,%1,%2,%3}, [%4];"
                 : "=r"(r[0]), "=r"(r[1]), "=r"(r[2]), "=r"(r[3]) : "r"(a));
}
__device__ __forceinline__ void mma_f16(float* c, const uint32_t* a, uint32_t b0, uint32_t b1)
{
    asm volatile("mma.sync.aligned.m16n8k16.row.col.f32.f16.f16.f32 "
                 "{%0,%1,%2,%3}, {%4,%5,%6,%7}, {%8,%9}, {%0,%1,%2,%3};"
                 : "+f"(c[0]), "+f"(c[1]), "+f"(c[2]), "+f"(c[3])
                 : "r"(a[0]), "r"(a[1]), "r"(a[2]), "r"(a[3]), "r"(b0), "r"(b1));
}
__device__ __forceinline__ void cp16(uint32_t dst, const void* src)
{
    asm volatile("cp.async.cg.shared.global [%0], [%1], 16;" :: "r"(dst), "l"(src) : "memory");
}
__device__ __forceinline__ void cp_commit_wait()
{
    asm volatile("cp.async.commit_group;\ncp.async.wait_group 0;" ::: "memory");
}

// ---------------- message GEMM: msg[p] = relu(hh[src(p)] + eattr[eid(p)]@We + be) ----------------
#define MG_HS   (128 * LDP * 2)
#define MG_AE   (MG_HS + 2 * 128 * EPITCH * 2)
#define MG_W    (MG_AE + 2 * 16 * LDP * 2)
#define MG_SMEM (MG_W + 512 + 256)

__global__ __launch_bounds__(256, 3)
void msggemm_kernel(const float* __restrict__ eattr,
                    const float* __restrict__ We, const float* __restrict__ be,
                    const __half* __restrict__ hh, __half* __restrict__ msg, int E)
{
    extern __shared__ char sm[];
    __half* Hs  = (__half*)sm;                   // [128][LDP]
    __half* Aeh = (__half*)(sm + MG_HS);         // [128][EPITCH]
    __half* Ael = Aeh + 128 * EPITCH;
    __half* Wh  = (__half*)(sm + MG_AE);         // [16][LDP]
    __half* Wl  = Wh + 16 * LDP;
    float* sb   = (float*)(sm + MG_W);
    uint32_t sbH = (uint32_t)__cvta_generic_to_shared(Hs);

    const int tid = threadIdx.x;
    const int warp = tid >> 5, lane = tid & 31;
    const int p0 = blockIdx.x * 128;

#pragma unroll
    for (int i = 0; i < 8; i++) {
        int j = tid + i * 256;
        int rowp = j >> 4, c = j & 15;
        int p = p0 + rowp;
        int s = (p < E) ? __ldg(&g_epack[p]).x : 0;
        cp16(sbH + rowp * (LDP * 2) + c * 16, (const char*)(hh + (size_t)s * CH) + c * 16);
    }

    for (int i = tid; i < 2048; i += 256) {
        int k = i >> 7, n = i & 127;
        float v = __ldg(We + i);
        __half h = __float2half_rn(v);
        Wh[k * LDP + n] = h;
        Wl[k * LDP + n] = __float2half_rn(v - __half2float(h));
    }
    if (tid < 128) sb[tid] = __ldg(be + tid);

    {
        int rowp = tid >> 1;
        int hoff = (tid & 1) * 8;
        int p = p0 + rowp;
        float4 v0 = make_float4(0.f, 0.f, 0.f, 0.f), v1 = v0;
        if (p < E) {
            int eid = __ldg(&g_epack[p]).y;
            const float4* ea = (const float4*)eattr + (size_t)eid * 4 + (tid & 1) * 2;
            v0 = __ldg(ea);
            v1 = __ldg(ea + 1);
        }
        *(uint2*)(Aeh + rowp * EPITCH + hoff)     = make_uint2(pack_h2_hi(v0.x, v0.y), pack_h2_hi(v0.z, v0.w));
        *(uint2*)(Aeh + rowp * EPITCH + hoff + 4) = make_uint2(pack_h2_hi(v1.x, v1.y), pack_h2_hi(v1.z, v1.w));
        *(uint2*)(Ael + rowp * EPITCH + hoff)     = make_uint2(pack_h2_lo(v0.x, v0.y), pack_h2_lo(v0.z, v0.w));
        *(uint2*)(Ael + rowp * EPITCH + hoff + 4) = make_uint2(pack_h2_lo(v1.x, v1.y), pack_h2_lo(v1.z, v1.w));
    }
    cp_commit_wait();
    __syncthreads();

    const int wr0 = warp * 16;
    const int arow = wr0 + (lane & 15);
    const int aoff = (lane >> 4) << 3;

    uint32_t ah[4], al[4];
    ldsm_x4(ah, Aeh + arow * EPITCH + aoff);
    ldsm_x4(al, Ael + arow * EPITCH + aoff);

    const int brow = (lane & 15);
    const int cb = (lane & 3) * 2;
    const int rl0 = wr0 + (lane >> 2);
    const int r0 = p0 + rl0;

#pragma unroll
    for (int nh = 0; nh < 2; nh++) {
        float acc[8][4];
#pragma unroll
        for (int t = 0; t < 8; t++)
#pragma unroll
            for (int j = 0; j < 4; j++) acc[t][j] = 0.f;
#pragma unroll
        for (int ng = 0; ng < 4; ng++) {
            const int n0 = nh * 64 + ng * 16;
            uint32_t bh[4], bl[4];
            ldsm_x4_t(bh, Wh + brow * LDP + n0 + aoff);
            ldsm_x4_t(bl, Wl + brow * LDP + n0 + aoff);
            mma_f16(acc[ng * 2],     ah, bh[0], bh[1]);
            mma_f16(acc[ng * 2],     al, bh[0], bh[1]);
            mma_f16(acc[ng * 2],     ah, bl[0], bl[1]);
            mma_f16(acc[ng * 2 + 1], ah, bh[2], bh[3]);
            mma_f16(acc[ng * 2 + 1], al, bh[2], bh[3]);
            mma_f16(acc[ng * 2 + 1], ah, bl[2], bl[3]);
        }
#pragma unroll
        for (int t = 0; t < 8; t++) {
            const int n = nh * 64 + t * 8 + cb;
            const float b0 = sb[n], b1 = sb[n + 1];
            {
                float2 hv = __half22float2(*(__half2*)(Hs + (size_t)rl0 * LDP + n));
                float m0 = fmaxf(hv.x + acc[t][0] + b0, 0.f);
                float m1 = fmaxf(hv.y + acc[t][1] + b1, 0.f);
                if (r0 < E)
                    *(uint32_t*)(msg + (size_t)r0 * CH + n) = pack_h2_hi(m0, m1);
            }
            {
                float2 hv = __half22float2(*(__half2*)(Hs + (size_t)(rl0 + 8) * LDP + n));
                float m0 = fmaxf(hv.x + acc[t][2] + b0, 0.f);
                float m1 = fmaxf(hv.y + acc[t][3] + b1, 0.f);
                if (r0 + 8 < E)
                    *(uint32_t*)(msg + (size_t)(r0 + 8) * CH + n) = pack_h2_hi(m0, m1);
            }
        }
    }
}

// ---------------- sequential aggregation ----------------
__global__ __launch_bounds__(256)
void aggregate_kernel(const __half* __restrict__ hh, const __half* __restrict__ hl,
                      const __half* __restrict__ msg, const float* __restrict__ epsp,
                      float* __restrict__ z, int N)
{
    const float epc = 1.0f + __ldg(epsp);
    const int tid = threadIdx.x;
    const int lane = tid & 31;
    int gw = (blockIdx.x * 256 + tid) >> 5;
    int nw = (gridDim.x * 256) >> 5;

    for (int n = gw; n < N; n += nw) {
        uint2 uh = __ldg((const uint2*)(hh + (size_t)n * CH) + lane);
        uint2 ul = __ldg((const uint2*)(hl + (size_t)n * CH) + lane);
        float2 h01 = __half22float2(*(__half2*)&uh.x);
        float2 h23 = __half22float2(*(__half2*)&uh.y);
        float2 l01 = __half22float2(*(__half2*)&ul.x);
        float2 l23 = __half22float2(*(__half2*)&ul.y);
        float4 acc;
        acc.x = epc * (h01.x + l01.x);
        acc.y = epc * (h01.y + l01.y);
        acc.z = epc * (h23.x + l23.x);
        acc.w = epc * (h23.y + l23.y);

        const int p0 = __ldg(&g_off[n]);
        const int p1 = __ldg(&g_off[n + 1]);

        uint2 euA = make_uint2(0, 0), euB = euA;
        if (p0 < p1)     euA = __ldg((const uint2*)(msg + (size_t)p0 * CH) + lane);
        if (p0 + 1 < p1) euB = __ldg((const uint2*)(msg + (size_t)(p0 + 1) * CH) + lane);
        for (int p = p0; p < p1; ++p) {
            uint2 ce = euA;
            euA = euB;
            if (p + 2 < p1) euB = __ldg((const uint2*)(msg + (size_t)(p + 2) * CH) + lane);
            float2 f01 = __half22float2(*(__half2*)&ce.x);
            float2 f23 = __half22float2(*(__half2*)&ce.y);
            acc.x += f01.x;
            acc.y += f01.y;
            acc.z += f23.x;
            acc.w += f23.y;
        }
        *(float4*)(z + (size_t)n * CH + lane * 4) = acc;
    }
}

// stage 64-row A tile (fp32 source) into fp16 hi/lo planes
__device__ __forceinline__ void stage_a_f16_64(const float* __restrict__ A,
                                               __half* Ah, __half* Al,
                                               int tid, int row0, int M)
{
#pragma unroll
    for (int i = 0; i < 8; i++) {
        int idx = tid + i * 256;
        int r = idx >> 5, c4 = idx & 31;
        int g = row0 + r;
        float4 v = make_float4(0.f, 0.f, 0.f, 0.f);
        if (g < M) v = __ldg((const float4*)(A + (size_t)g * CH) + c4);
        *(uint2*)(Ah + r * LDP + c4 * 4) = make_uint2(pack_h2_hi(v.x, v.y), pack_h2_hi(v.z, v.w));
        *(uint2*)(Al + r * LDP + c4 * 4) = make_uint2(pack_h2_lo(v.x, v.y), pack_h2_lo(v.z, v.w));
    }
}

// 2-term fp16 pass, warp tile 16 rows x 64 cols
__device__ __forceinline__ void mma_pass16(const __half* Ah, const __half* Al,
                                           const __half* Bh,
                                           int lane, int wr0, int wc0, float acc[8][4])
{
#pragma unroll
    for (int t = 0; t < 8; t++)
#pragma unroll
        for (int j = 0; j < 4; j++) acc[t][j] = 0.f;

    const int arow = wr0 + (lane & 15);
    const int aoff = (lane >> 4) << 3;

#pragma unroll
    for (int kc = 0; kc < 8; kc++) {
        const int kb = kc * 16;
        uint32_t ah[4], al[4];
        ldsm_x4(ah, Ah + (size_t)arow * LDP + kb + aoff);
        ldsm_x4(al, Al + (size_t)arow * LDP + kb + aoff);
        const int brow = kb + (lane & 15);
#pragma unroll
        for (int ng = 0; ng < 4; ng++) {
            uint32_t b[4];
            ldsm_x4_t(b, Bh + (size_t)brow * LDP + wc0 + ng * 16 + aoff);
            mma_f16(acc[ng * 2],     ah, b[0], b[1]);
            mma_f16(acc[ng * 2],     al, b[0], b[1]);
            mma_f16(acc[ng * 2 + 1], ah, b[2], b[3]);
            mma_f16(acc[ng * 2 + 1], al, b[2], b[3]);
        }
    }
}

__device__ __forceinline__ void z_to_planes16(__half* Ah, __half* Al, const float* sb,
                                              float acc[8][4], int lane, int wr0, int wc0)
{
    const int cb = (lane & 3) * 2;
    const int rl = wr0 + (lane >> 2);
#pragma unroll
    for (int t = 0; t < 8; t++) {
        const int n = wc0 + t * 8 + cb;
        const float b0 = sb[n], b1v = sb[n + 1];
        float z0 = fmaxf(acc[t][0] + b0, 0.f);
        float z1 = fmaxf(acc[t][1] + b1v, 0.f);
        float z2 = fmaxf(acc[t][2] + b0, 0.f);
        float z3 = fmaxf(acc[t][3] + b1v, 0.f);
        *(uint32_t*)(Ah + (size_t)rl * LDP + n)       = pack_h2_hi(z0, z1);
        *(uint32_t*)(Al + (size_t)rl * LDP + n)       = pack_h2_lo(z0, z1);
        *(uint32_t*)(Ah + (size_t)(rl + 8) * LDP + n) = pack_h2_hi(z2, z3);
        *(uint32_t*)(Al + (size_t)(rl + 8) * LDP + n) = pack_h2_lo(z2, z3);
    }
}

__device__ __forceinline__ void planes_to_global64(const __half* Ah, const __half* Al,
                                                   __half* oh, __half* ol,
                                                   int tid, int row0, int M)
{
#pragma unroll
    for (int i = 0; i < 4; i++) {
        int j = tid + i * 256;
        int r = j >> 4, c = j & 15;
        int g = row0 + r;
        if (g < M) {
            uint4 vh = *(const uint4*)((const char*)Ah + (size_t)r * LDP * 2 + c * 16);
            uint4 vl = *(const uint4*)((const char*)Al + (size_t)r * LDP * 2 + c * 16);
            *(uint4*)((char*)(oh + (size_t)g * CH) + c * 16) = vh;
            *(uint4*)((char*)(ol + (size_t)g * CH) + c * 16) = vl;
        }
    }
}

// ---------------- encoder GEMM (64-row tile, occ 3) ----------------
#define G1_SMEM (2 * HPLANE_B + PLANE_B + 512)

__global__ __launch_bounds__(256, 3)
void gemm_tc(const float* __restrict__ A, const float4* __restrict__ WhP,
             const float* __restrict__ bias,
             __half* __restrict__ oh, __half* __restrict__ ol, int M)
{
    extern __shared__ char sm[];
    __half* Ah = (__half*)sm;
    __half* Al = Ah + 64 * LDP;
    __half* Wh = Al + 64 * LDP;
    float* sbias = (float*)(sm + 2 * HPLANE_B + PLANE_B);
    uint32_t sbW = (uint32_t)__cvta_generic_to_shared(Wh);

    const int tid = threadIdx.x;
    const int warp = tid >> 5, lane = tid & 31;
    const int row0 = blockIdx.x * 64;

#pragma unroll
    for (int i = 0; i < 9; i++) {
        int j = tid + i * 256;
        if (j < PLANE_F4) cp16(sbW + j * 16, WhP + j);
    }
    if (tid < 128) sbias[tid] = __ldg(bias + tid);

    stage_a_f16_64(A, Ah, Al, tid, row0, M);
    cp_commit_wait();
    __syncthreads();

    const int wr0 = (warp >> 1) * 16;
    const int wc0 = (warp & 1) * 64;

    float acc[8][4];
    mma_pass16(Ah, Al, Wh, lane, wr0, wc0, acc);
    __syncthreads();

    z_to_planes16(Ah, Al, sbias, acc, lane, wr0, wc0);
    __syncthreads();
    planes_to_global64(Ah, Al, oh, ol, tid, row0, M);
}

// ---------------- fused 2-layer MLP (64-row tile, occ 3, W reloaded) ----------------
#define G2_SMEM (2 * HPLANE_B + PLANE_B + 1024)

template <bool OUT16>
__global__ __launch_bounds__(256, 3)
void gemm2_tc(const float* __restrict__ A,
              const float4* __restrict__ W1P, const float4* __restrict__ W2P,
              const float* __restrict__ b1, const float* __restrict__ b2,
              float* __restrict__ out, __half* __restrict__ oh, __half* __restrict__ ol,
              int M)
{
    extern __shared__ char sm[];
    __half* Ah = (__half*)sm;
    __half* Al = Ah + 64 * LDP;
    __half* Wp = Al + 64 * LDP;
    float* sb1 = (float*)(sm + 2 * HPLANE_B + PLANE_B);
    float* sb2 = sb1 + 128;
    uint32_t sbW = (uint32_t)__cvta_generic_to_shared(Wp);

    const int tid = threadIdx.x;
    const int warp = tid >> 5, lane = tid & 31;
    const int row0 = blockIdx.x * 64;

#pragma unroll
    for (int i = 0; i < 9; i++) {
        int j = tid + i * 256;
        if (j < PLANE_F4) cp16(sbW + j * 16, W1P + j);
    }
    if (tid < 128) sb1[tid] = __ldg(b1 + tid);
    else           sb2[tid - 128] = __ldg(b2 + tid - 128);

    stage_a_f16_64(A, Ah, Al, tid, row0, M);
    cp_commit_wait();
    __syncthreads();

    const int wr0 = (warp >> 1) * 16;
    const int wc0 = (warp & 1) * 64;

    float acc[8][4];
    mma_pass16(Ah, Al, Wp, lane, wr0, wc0, acc);
    __syncthreads();

#pragma unroll
    for (int i = 0; i < 9; i++) {
        int j = tid + i * 256;
        if (j < PLANE_F4) cp16(sbW + j * 16, W2P + j);
    }
    z_to_planes16(Ah, Al, sb1, acc, lane, wr0, wc0);
    cp_commit_wait();
    __syncthreads();

    mma_pass16(Ah, Al, Wp, lane, wr0, wc0, acc);
    __syncthreads();

    if (OUT16) {
        z_to_planes16(Ah, Al, sb2, acc, lane, wr0, wc0);
        __syncthreads();
        planes_to_global64(Ah, Al, oh, ol, tid, row0, M);
    } else {
        float* ftile = (float*)sm;
        const int cb = (lane & 3) * 2;
        const int rl = wr0 + (lane >> 2);
#pragma unroll
        for (int t = 0; t < 8; t++) {
            const int n = wc0 + t * 8 + cb;
            const float b0 = sb2[n], b1v = sb2[n + 1];
            float2 o0 = make_float2(fmaxf(acc[t][0] + b0, 0.f),
                                    fmaxf(acc[t][1] + b1v, 0.f));
            float2 o1 = make_float2(fmaxf(acc[t][2] + b0, 0.f),
                                    fmaxf(acc[t][3] + b1v, 0.f));
            *(float2*)(ftile + (size_t)rl * FT_PITCH + n)       = o0;
            *(float2*)(ftile + (size_t)(rl + 8) * FT_PITCH + n) = o1;
        }
        __syncthreads();
#pragma unroll
        for (int i = 0; i < 8; i++) {
            int j = tid + i * 256;
            int r = j >> 5, c = j & 31;
            int g = row0 + r;
            if (g < M) {
                float4 v = *(const float4*)(ftile + (size_t)r * FT_PITCH + c * 4);
                *(float4*)(out + (size_t)g * CH + c * 4) = v;
            }
        }
    }
}

// ---------------- launch ----------------
extern "C" void kernel_launch(void* const* d_in, const int* in_sizes, int n_in,
                              void* d_out, int out_size)
{
    const float* x     = (const float*)d_in[0];
    const void*  eidx  = d_in[1];
    const float* eattr = (const float*)d_in[2];
    const float* W_enc = (const float*)d_in[3];
    const float* b_enc = (const float*)d_in[4];
    const float* We1   = (const float*)d_in[5];
    const float* be1   = (const float*)d_in[6];
    const float* W11   = (const float*)d_in[7];
    const float* b11   = (const float*)d_in[8];
    const float* W12   = (const float*)d_in[9];
    const float* b12   = (const float*)d_in[10];
    const float* eps1  = (const float*)d_in[11];
    const float* We2   = (const float*)d_in[12];
    const float* be2   = (const float*)d_in[13];
    const float* W21   = (const float*)d_in[14];
    const float* b21   = (const float*)d_in[15];
    const float* W22   = (const float*)d_in[16];
    const float* b22   = (const float*)d_in[17];
    const float* eps2  = (const float*)d_in[18];

    const int N = in_sizes[0] / CH;
    const int E = in_sizes[2] / 16;
    float* out = (float*)d_out;

    float* aggP;
    float4* wpl;
    __half *msgP, *hhP, *hlP;
    cudaGetSymbolAddress((void**)&aggP, g_agg);
    cudaGetSymbolAddress((void**)&wpl, g_wplanes);
    cudaGetSymbolAddress((void**)&msgP, g_msg);
    cudaGetSymbolAddress((void**)&hhP, g_hh);
    cudaGetSymbolAddress((void**)&hlP, g_hl);

    cudaFuncSetAttribute((const void*)gemm_tc,
                         cudaFuncAttributeMaxDynamicSharedMemorySize, G1_SMEM);
    cudaFuncSetAttribute((const void*)gemm2_tc<true>,
                         cudaFuncAttributeMaxDynamicSharedMemorySize, G2_SMEM);
    cudaFuncSetAttribute((const void*)gemm2_tc<false>,
                         cudaFuncAttributeMaxDynamicSharedMemorySize, G2_SMEM);
    cudaFuncSetAttribute((const void*)msggemm_kernel,
                         cudaFuncAttributeMaxDynamicSharedMemorySize, MG_SMEM);

    const int nb = (N + 1023) / 1024;
    const int gb = (N + 63) / 64;
    const int ge = (E + 127) / 128;

    // fork-join: CSR build runs on a side stream, overlapped with weight prep +
    // encoder GEMM on the main (capture) stream. Host objects are created fresh
    // per call and not destroyed (kernel_launch runs only a handful of times;
    // no device memory involved).
    cudaStream_t s2;
    cudaStreamCreateWithFlags(&s2, cudaStreamNonBlocking);
    cudaEvent_t evFork, evJoin;
    cudaEventCreateWithFlags(&evFork, cudaEventDisableTiming);
    cudaEventCreateWithFlags(&evJoin, cudaEventDisableTiming);

    init_kernel<<<nb, 1024>>>((const unsigned*)eidx, 2 * E, N);
    cudaEventRecord(evFork, 0);
    cudaStreamWaitEvent(s2, evFork, 0);

    // side stream: CSR build chain
    convert_hist_kernel<<<(E + 255) / 256, 256, 0, s2>>>(eidx, E);
    scan1_kernel<<<nb, 1024, 0, s2>>>(N);
    scan2_kernel<<<1, 256, 0, s2>>>(nb, N, E);
    scan3_kernel<<<nb, 1024, 0, s2>>>(N);
    place_kernel<<<(E + 255) / 256, 256, 0, s2>>>(E);
    cudaEventRecord(evJoin, s2);

    // main stream: weights + encoder GEMM (overlaps CSR build)
    prep_weights<<<(5 * 128 * LDP + 255) / 256, 256>>>(W_enc, W11, W12, W21, W22);
    gemm_tc<<<gb, 256, G1_SMEM>>>(x, wpl, b_enc, hhP, hlP, N);

    cudaStreamWaitEvent(0, evJoin, 0);

    // ---- conv1 ----
    msggemm_kernel<<<ge, 256, MG_SMEM>>>(eattr, We1, be1, hhP, msgP, E);
    aggregate_kernel<<<2368, 256>>>(hhP, hlP, msgP, eps1, aggP, N);
    gemm2_tc<true><<<gb, 256, G2_SMEM>>>(aggP, wpl + 1 * PLANE_F4, wpl + 2 * PLANE_F4,
                                         b11, b12, nullptr, hhP, hlP, N);

    // ---- conv2 ----
    msggemm_kernel<<<ge, 256, MG_SMEM>>>(eattr, We2, be2, hhP, msgP, E);
    aggregate_kernel<<<2368, 256>>>(hhP, hlP, msgP, eps2, aggP, N);
    gemm2_tc<false><<<gb, 256, G2_SMEM>>>(aggP, wpl + 3 * PLANE_F4, wpl + 4 * PLANE_F4,
                                          b21, b22, out, nullptr, nullptr, N);
}

// round 15
// speedup vs baseline: 1.4213x; 1.2910x over previous
#include <cuda_runtime.h>
#include <cuda_fp16.h>
#include <cstdint>
#include <cstddef>

#define NMAX 200000
#define EMAX 600000
#define CH 128
#define LDP 136                      // padded row pitch in fp16 elems
#define EPITCH 24                    // eattr tile pitch (16 cols + pad)
#define PLANE_B (128 * LDP * 2)      // full 128-row plane bytes (W planes)
#define HPLANE_B (64 * LDP * 2)      // 64-row A/Z plane bytes
#define PLANE_F4 (PLANE_B / 16)      // 2176 float4 per full plane
#define FT_PITCH 132                 // fp32 staging pitch

// ---------------- scratch (device globals; no allocation allowed) ----------------
__device__ __half g_hh[(size_t)NMAX * CH];   // h hi plane (fp16)
__device__ __half g_hl[(size_t)NMAX * CH];   // h lo plane (fp16 residual)
__device__ float g_agg[(size_t)NMAX * CH];   // z accumulator (seeded with (1+eps)h)
__device__ int   g_src[EMAX];
__device__ int   g_dst[EMAX];
__device__ int2  g_epack[EMAX];              // (src, eid) in CSR order
__device__ int   g_pdst[EMAX];               // dst in CSR order
__device__ int   g_cnt[NMAX];
__device__ int   g_off[NMAX + 1];
__device__ int   g_cur[NMAX];
__device__ int   g_bsum[256];
__device__ int   g_bbase[256];
__device__ int   g_idx64;
__device__ float4 g_wplanes[5 * PLANE_F4];   // 5 node-weights, fp16 planes [k][n]

// ---------------- init: zero counts + edge_index dtype sniff ----------------
__global__ void init_kernel(const unsigned* __restrict__ p, int nwords, int N)
{
    __shared__ unsigned s[32];
    int gi = blockIdx.x * 1024 + threadIdx.x;
    if (gi < N) g_cnt[gi] = 0;
    if (blockIdx.x == 0) {
        unsigned v = 0;
        for (int i = threadIdx.x; i < 4096; i += 1024) {
            int w = 2 * i + 1;
            if (w < nwords) v |= p[w];
        }
#pragma unroll
        for (int o = 16; o > 0; o >>= 1) v |= __shfl_xor_sync(0xffffffffu, v, o);
        int lane = threadIdx.x & 31, wid = threadIdx.x >> 5;
        if (lane == 0) s[wid] = v;
        __syncthreads();
        if (threadIdx.x == 0) {
            unsigned r = 0;
            for (int i = 0; i < 32; i++) r |= s[i];
            g_idx64 = (r == 0) ? 1 : 0;
        }
    }
}

// ---------------- weight prep ----------------
__global__ void prep_weights(const float* __restrict__ W0, const float* __restrict__ W1,
                             const float* __restrict__ W2, const float* __restrict__ W3,
                             const float* __restrict__ W4)
{
    int idx = blockIdx.x * blockDim.x + threadIdx.x;
    if (idx >= 5 * 128 * LDP) return;
    int wi = idx / (128 * LDP);
    int e  = idx % (128 * LDP);
    int k = e / LDP, n = e % LDP;
    const float* W = (wi == 0) ? W0 : (wi == 1) ? W1 : (wi == 2) ? W2 : (wi == 3) ? W3 : W4;
    __half h = __float2half_rn(0.f);
    if (n < 128) h = __float2half_rn(__ldg(W + k * 128 + n));
    ((__half*)g_wplanes)[(size_t)wi * 128 * LDP + e] = h;
}

// ---------------- CSR build ----------------
__global__ void convert_hist_kernel(const void* __restrict__ ei, int E)
{
    int i = blockIdx.x * blockDim.x + threadIdx.x;
    if (i >= E) return;
    int s, d;
    if (g_idx64) {
        const long long* p = (const long long*)ei;
        s = (int)p[i];
        d = (int)p[(size_t)E + i];
    } else {
        const int* p = (const int*)ei;
        s = p[i];
        d = p[E + i];
    }
    g_src[i] = s;
    g_dst[i] = d;
    atomicAdd(&g_cnt[d], 1);
}

__global__ void scan1_kernel(int N)
{
    __shared__ int s[32];
    int idx = blockIdx.x * 1024 + threadIdx.x;
    int v = (idx < N) ? g_cnt[idx] : 0;
    int t = v;
#pragma unroll
    for (int o = 16; o > 0; o >>= 1) t += __shfl_xor_sync(0xffffffffu, t, o);
    if ((threadIdx.x & 31) == 0) s[threadIdx.x >> 5] = t;
    __syncthreads();
    if (threadIdx.x == 0) {
        int r = 0;
        for (int i = 0; i < 32; i++) r += s[i];
        g_bsum[blockIdx.x] = r;
    }
}

__global__ void scan2_kernel(int nb, int N, int E)
{
    __shared__ int s[256];
    int t = threadIdx.x;
    int v = (t < nb) ? g_bsum[t] : 0;
    s[t] = v;
    __syncthreads();
#pragma unroll
    for (int o = 1; o < 256; o <<= 1) {
        int nv = s[t];
        if (t >= o) nv += s[t - o];
        __syncthreads();
        s[t] = nv;
        __syncthreads();
    }
    if (t < nb) g_bbase[t] = s[t] - v;
    if (t == 0) g_off[N] = E;
}

__global__ void scan3_kernel(int N)
{
    __shared__ int s[1024];
    int idx = blockIdx.x * 1024 + threadIdx.x;
    int t = threadIdx.x;
    int v = (idx < N) ? g_cnt[idx] : 0;
    s[t] = v;
    __syncthreads();
#pragma unroll
    for (int o = 1; o < 1024; o <<= 1) {
        int nv = s[t];
        if (t >= o) nv += s[t - o];
        __syncthreads();
        s[t] = nv;
        __syncthreads();
    }
    if (idx < N) {
        int excl = g_bbase[blockIdx.x] + s[t] - v;
        g_off[idx] = excl;
        g_cur[idx] = excl;
    }
}

__global__ void place_kernel(int E)
{
    int i = blockIdx.x * blockDim.x + threadIdx.x;
    if (i >= E) return;
    int d = g_dst[i];
    int p = atomicAdd(&g_cur[d], 1);
    g_epack[p] = make_int2(g_src[i], i);
    g_pdst[p] = d;
}

// ---------------- fp16 helpers ----------------
__device__ __forceinline__ uint32_t pack_h2_hi(float a, float b)
{
    __half ha = __float2half_rn(a), hb = __float2half_rn(b);
    return ((uint32_t)__half_as_ushort(hb) << 16) | __half_as_ushort(ha);
}
__device__ __forceinline__ uint32_t pack_h2_lo(float a, float b)
{
    __half ha = __float2half_rn(a), hb = __float2half_rn(b);
    __half la = __float2half_rn(a - __half2float(ha));
    __half lb = __float2half_rn(b - __half2float(hb));
    return ((uint32_t)__half_as_ushort(lb) << 16) | __half_as_ushort(la);
}
__device__ __forceinline__ void ldsm_x4(uint32_t* r, const void* p)
{
    uint32_t a = (uint32_t)__cvta_generic_to_shared(p);
    asm volatile("ldmatrix.sync.aligned.m8n8.x4.shared.b16 {%0,%1,%2,%3}, [%4];"
                 : "=r"(r[0]), "=r"(r[1]), "=r"(r[2]), "=r"(r[3]) : "r"(a));
}
__device__ __forceinline__ void ldsm_x4_t(uint32_t* r, const void* p)
{
    uint32_t a = (uint32_t)__cvta_generic_to_shared(p);
    asm volatile("ldmatrix.sync.aligned.m8n8.x4.trans.shared.b16 {%0,%1,%2,%3}, [%4];"
                 : "=r"(r[0]), "=r"(r[1]), "=r"(r[2]), "=r"(r[3]) : "r"(a));
}
__device__ __forceinline__ void mma_f16(float* c, const uint32_t* a, uint32_t b0, uint32_t b1)
{
    asm volatile("mma.sync.aligned.m16n8k16.row.col.f32.f16.f16.f32 "
                 "{%0,%1,%2,%3}, {%4,%5,%6,%7}, {%8,%9}, {%0,%1,%2,%3};"
                 : "+f"(c[0]), "+f"(c[1]), "+f"(c[2]), "+f"(c[3])
                 : "r"(a[0]), "r"(a[1]), "r"(a[2]), "r"(a[3]), "r"(b0), "r"(b1));
}
__device__ __forceinline__ void cp16(uint32_t dst, const void* src)
{
    asm volatile("cp.async.cg.shared.global [%0], [%1], 16;" :: "r"(dst), "l"(src) : "memory");
}
__device__ __forceinline__ void cp_commit_wait()
{
    asm volatile("cp.async.commit_group;\ncp.async.wait_group 0;" ::: "memory");
}
__device__ __forceinline__ void red_add4(float* gp, float4 v)
{
    size_t ga = __cvta_generic_to_global(gp);
    asm volatile("red.global.add.v4.f32 [%0], {%1,%2,%3,%4};"
                 :: "l"(ga), "f"(v.x), "f"(v.y), "f"(v.z), "f"(v.w) : "memory");
}

// ---------------- message GEMM + in-CTA segment reduction ----------------
// msg[slot] = relu(hh[src] + eattr[eid]@We + be) built in smem, then per-warp
// run-length reduction over CSR-sorted dst; partials red.add'ed into agg
// (agg pre-seeded with (1+eps)*h by the producer GEMM epilogue).
#define MG_HS   (128 * LDP * 2)
#define MG_AE   (MG_HS + 2 * 128 * EPITCH * 2)
#define MG_W    (MG_AE + 2 * 16 * LDP * 2)
#define MG_SMEM (MG_W + 512 + 512 + 256)

__global__ __launch_bounds__(256, 3)
void msggemm_kernel(const float* __restrict__ eattr,
                    const float* __restrict__ We, const float* __restrict__ be,
                    const __half* __restrict__ hh, float* __restrict__ agg, int E)
{
    extern __shared__ char sm[];
    __half* Hs  = (__half*)sm;                   // [128][LDP]: h rows, then msg rows
    __half* Aeh = (__half*)(sm + MG_HS);         // [128][EPITCH]
    __half* Ael = Aeh + 128 * EPITCH;
    __half* Wh  = (__half*)(sm + MG_AE);         // [16][LDP]
    __half* Wl  = Wh + 16 * LDP;
    float* sb   = (float*)(sm + MG_W);
    int*   sdst = (int*)(sm + MG_W + 512);
    uint32_t sbH = (uint32_t)__cvta_generic_to_shared(Hs);

    const int tid = threadIdx.x;
    const int warp = tid >> 5, lane = tid & 31;
    const int p0 = blockIdx.x * 128;

#pragma unroll
    for (int i = 0; i < 8; i++) {
        int j = tid + i * 256;
        int rowp = j >> 4, c = j & 15;
        int p = p0 + rowp;
        int s = (p < E) ? __ldg(&g_epack[p]).x : 0;
        cp16(sbH + rowp * (LDP * 2) + c * 16, (const char*)(hh + (size_t)s * CH) + c * 16);
    }

    for (int i = tid; i < 2048; i += 256) {
        int k = i >> 7, n = i & 127;
        float v = __ldg(We + i);
        __half h = __float2half_rn(v);
        Wh[k * LDP + n] = h;
        Wl[k * LDP + n] = __float2half_rn(v - __half2float(h));
    }
    if (tid < 128) sb[tid] = __ldg(be + tid);
    else           sdst[tid - 128] = (p0 + tid - 128 < E) ? __ldg(&g_pdst[p0 + tid - 128]) : -1;
    if (tid < 128) sdst[tid] = 0;  // placeholder; fixed below
    __syncwarp();
    if (tid < 128) sdst[tid] = (p0 + tid < E) ? __ldg(&g_pdst[p0 + tid]) : -1;

    {
        int rowp = tid >> 1;
        int hoff = (tid & 1) * 8;
        int p = p0 + rowp;
        float4 v0 = make_float4(0.f, 0.f, 0.f, 0.f), v1 = v0;
        if (p < E) {
            int eid = __ldg(&g_epack[p]).y;
            const float4* ea = (const float4*)eattr + (size_t)eid * 4 + (tid & 1) * 2;
            v0 = __ldg(ea);
            v1 = __ldg(ea + 1);
        }
        *(uint2*)(Aeh + rowp * EPITCH + hoff)     = make_uint2(pack_h2_hi(v0.x, v0.y), pack_h2_hi(v0.z, v0.w));
        *(uint2*)(Aeh + rowp * EPITCH + hoff + 4) = make_uint2(pack_h2_hi(v1.x, v1.y), pack_h2_hi(v1.z, v1.w));
        *(uint2*)(Ael + rowp * EPITCH + hoff)     = make_uint2(pack_h2_lo(v0.x, v0.y), pack_h2_lo(v0.z, v0.w));
        *(uint2*)(Ael + rowp * EPITCH + hoff + 4) = make_uint2(pack_h2_lo(v1.x, v1.y), pack_h2_lo(v1.z, v1.w));
    }
    cp_commit_wait();
    __syncthreads();

    const int wr0 = warp * 16;
    const int arow = wr0 + (lane & 15);
    const int aoff = (lane >> 4) << 3;

    uint32_t ah[4], al[4];
    ldsm_x4(ah, Aeh + arow * EPITCH + aoff);
    ldsm_x4(al, Ael + arow * EPITCH + aoff);

    const int brow = (lane & 15);
    const int cb = (lane & 3) * 2;
    const int rl0 = wr0 + (lane >> 2);

    // compute messages; overwrite Hs rows in place (each (row,col) slot is
    // read and then written by exactly the same thread)
#pragma unroll
    for (int nh = 0; nh < 2; nh++) {
        float acc[8][4];
#pragma unroll
        for (int t = 0; t < 8; t++)
#pragma unroll
            for (int j = 0; j < 4; j++) acc[t][j] = 0.f;
#pragma unroll
        for (int ng = 0; ng < 4; ng++) {
            const int n0 = nh * 64 + ng * 16;
            uint32_t bh[4], bl[4];
            ldsm_x4_t(bh, Wh + brow * LDP + n0 + aoff);
            ldsm_x4_t(bl, Wl + brow * LDP + n0 + aoff);
            mma_f16(acc[ng * 2],     ah, bh[0], bh[1]);
            mma_f16(acc[ng * 2],     al, bh[0], bh[1]);
            mma_f16(acc[ng * 2],     ah, bl[0], bl[1]);
            mma_f16(acc[ng * 2 + 1], ah, bh[2], bh[3]);
            mma_f16(acc[ng * 2 + 1], al, bh[2], bh[3]);
            mma_f16(acc[ng * 2 + 1], ah, bl[2], bl[3]);
        }
#pragma unroll
        for (int t = 0; t < 8; t++) {
            const int n = nh * 64 + t * 8 + cb;
            const float b0 = sb[n], b1 = sb[n + 1];
            {
                uint32_t* hp = (uint32_t*)(Hs + (size_t)rl0 * LDP + n);
                float2 hv = __half22float2(*(__half2*)hp);
                *hp = pack_h2_hi(fmaxf(hv.x + acc[t][0] + b0, 0.f),
                                 fmaxf(hv.y + acc[t][1] + b1, 0.f));
            }
            {
                uint32_t* hp = (uint32_t*)(Hs + (size_t)(rl0 + 8) * LDP + n);
                float2 hv = __half22float2(*(__half2*)hp);
                *hp = pack_h2_hi(fmaxf(hv.x + acc[t][2] + b0, 0.f),
                                 fmaxf(hv.y + acc[t][3] + b1, 0.f));
            }
        }
    }
    __syncthreads();

    // segment reduction: warp w scans slots [w*16, w*16+16); lane owns 4 channels
    {
        const int sbase = warp * 16;
        float4 racc = make_float4(0.f, 0.f, 0.f, 0.f);
        int cur = sdst[sbase];
#pragma unroll
        for (int i = 0; i < 16; i++) {
            int d = sdst[sbase + i];
            if (d != cur) {
                if (cur >= 0) red_add4(agg + (size_t)cur * CH + lane * 4, racc);
                racc = make_float4(0.f, 0.f, 0.f, 0.f);
                cur = d;
            }
            if (d >= 0) {
                uint2 mv = *(const uint2*)(Hs + (size_t)(sbase + i) * LDP + lane * 4);
                float2 f01 = __half22float2(*(__half2*)&mv.x);
                float2 f23 = __half22float2(*(__half2*)&mv.y);
                racc.x += f01.x;
                racc.y += f01.y;
                racc.z += f23.x;
                racc.w += f23.y;
            }
        }
        if (cur >= 0) red_add4(agg + (size_t)cur * CH + lane * 4, racc);
    }
}

// stage 64-row A tile (fp32 source) into fp16 hi/lo planes
__device__ __forceinline__ void stage_a_f16_64(const float* __restrict__ A,
                                               __half* Ah, __half* Al,
                                               int tid, int row0, int M)
{
#pragma unroll
    for (int i = 0; i < 8; i++) {
        int idx = tid + i * 256;
        int r = idx >> 5, c4 = idx & 31;
        int g = row0 + r;
        float4 v = make_float4(0.f, 0.f, 0.f, 0.f);
        if (g < M) v = __ldg((const float4*)(A + (size_t)g * CH) + c4);
        *(uint2*)(Ah + r * LDP + c4 * 4) = make_uint2(pack_h2_hi(v.x, v.y), pack_h2_hi(v.z, v.w));
        *(uint2*)(Al + r * LDP + c4 * 4) = make_uint2(pack_h2_lo(v.x, v.y), pack_h2_lo(v.z, v.w));
    }
}

// 2-term fp16 pass, warp tile 16 rows x 64 cols
__device__ __forceinline__ void mma_pass16(const __half* Ah, const __half* Al,
                                           const __half* Bh,
                                           int lane, int wr0, int wc0, float acc[8][4])
{
#pragma unroll
    for (int t = 0; t < 8; t++)
#pragma unroll
        for (int j = 0; j < 4; j++) acc[t][j] = 0.f;

    const int arow = wr0 + (lane & 15);
    const int aoff = (lane >> 4) << 3;

#pragma unroll
    for (int kc = 0; kc < 8; kc++) {
        const int kb = kc * 16;
        uint32_t ah[4], al[4];
        ldsm_x4(ah, Ah + (size_t)arow * LDP + kb + aoff);
        ldsm_x4(al, Al + (size_t)arow * LDP + kb + aoff);
        const int brow = kb + (lane & 15);
#pragma unroll
        for (int ng = 0; ng < 4; ng++) {
            uint32_t b[4];
            ldsm_x4_t(b, Bh + (size_t)brow * LDP + wc0 + ng * 16 + aoff);
            mma_f16(acc[ng * 2],     ah, b[0], b[1]);
            mma_f16(acc[ng * 2],     al, b[0], b[1]);
            mma_f16(acc[ng * 2 + 1], ah, b[2], b[3]);
            mma_f16(acc[ng * 2 + 1], al, b[2], b[3]);
        }
    }
}

__device__ __forceinline__ void z_to_planes16(__half* Ah, __half* Al, const float* sb,
                                              float acc[8][4], int lane, int wr0, int wc0)
{
    const int cb = (lane & 3) * 2;
    const int rl = wr0 + (lane >> 2);
#pragma unroll
    for (int t = 0; t < 8; t++) {
        const int n = wc0 + t * 8 + cb;
        const float b0 = sb[n], b1v = sb[n + 1];
        float z0 = fmaxf(acc[t][0] + b0, 0.f);
        float z1 = fmaxf(acc[t][1] + b1v, 0.f);
        float z2 = fmaxf(acc[t][2] + b0, 0.f);
        float z3 = fmaxf(acc[t][3] + b1v, 0.f);
        *(uint32_t*)(Ah + (size_t)rl * LDP + n)       = pack_h2_hi(z0, z1);
        *(uint32_t*)(Al + (size_t)rl * LDP + n)       = pack_h2_lo(z0, z1);
        *(uint32_t*)(Ah + (size_t)(rl + 8) * LDP + n) = pack_h2_hi(z2, z3);
        *(uint32_t*)(Al + (size_t)(rl + 8) * LDP + n) = pack_h2_lo(z2, z3);
    }
}

// coalesced copy of planes to global fp16 arrays + seed agg = epc * value (fp32)
__device__ __forceinline__ void planes_to_global64_agg(const __half* Ah, const __half* Al,
                                                       __half* oh, __half* ol,
                                                       float* agg, float epc,
                                                       int tid, int row0, int M)
{
#pragma unroll
    for (int i = 0; i < 4; i++) {
        int j = tid + i * 256;
        int r = j >> 4, c = j & 15;
        int g = row0 + r;
        if (g < M) {
            uint4 vh = *(const uint4*)((const char*)Ah + (size_t)r * LDP * 2 + c * 16);
            uint4 vl = *(const uint4*)((const char*)Al + (size_t)r * LDP * 2 + c * 16);
            *(uint4*)((char*)(oh + (size_t)g * CH) + c * 16) = vh;
            *(uint4*)((char*)(ol + (size_t)g * CH) + c * 16) = vl;
            // fp32 seed: epc * (hi + lo)
            float2 a0 = __half22float2(*(__half2*)&vh.x);
            float2 a1 = __half22float2(*(__half2*)&vh.y);
            float2 a2 = __half22float2(*(__half2*)&vh.z);
            float2 a3 = __half22float2(*(__half2*)&vh.w);
            float2 b0 = __half22float2(*(__half2*)&vl.x);
            float2 b1 = __half22float2(*(__half2*)&vl.y);
            float2 b2 = __half22float2(*(__half2*)&vl.z);
            float2 b3 = __half22float2(*(__half2*)&vl.w);
            float* ap = agg + (size_t)g * CH + c * 8;
            float4 o0 = make_float4(epc * (a0.x + b0.x), epc * (a0.y + b0.y),
                                    epc * (a1.x + b1.x), epc * (a1.y + b1.y));
            float4 o1 = make_float4(epc * (a2.x + b2.x), epc * (a2.y + b2.y),
                                    epc * (a3.x + b3.x), epc * (a3.y + b3.y));
            *(float4*)ap = o0;
            *(float4*)(ap + 4) = o1;
        }
    }
}

// ---------------- encoder GEMM (64-row tile, occ 3): writes h planes + agg seed ----------------
#define G1_SMEM (2 * HPLANE_B + PLANE_B + 512)

__global__ __launch_bounds__(256, 3)
void gemm_tc(const float* __restrict__ A, const float4* __restrict__ WhP,
             const float* __restrict__ bias, const float* __restrict__ epsp,
             __half* __restrict__ oh, __half* __restrict__ ol,
             float* __restrict__ agg, int M)
{
    extern __shared__ char sm[];
    __half* Ah = (__half*)sm;
    __half* Al = Ah + 64 * LDP;
    __half* Wh = Al + 64 * LDP;
    float* sbias = (float*)(sm + 2 * HPLANE_B + PLANE_B);
    uint32_t sbW = (uint32_t)__cvta_generic_to_shared(Wh);

    const int tid = threadIdx.x;
    const int warp = tid >> 5, lane = tid & 31;
    const int row0 = blockIdx.x * 64;

#pragma unroll
    for (int i = 0; i < 9; i++) {
        int j = tid + i * 256;
        if (j < PLANE_F4) cp16(sbW + j * 16, WhP + j);
    }
    if (tid < 128) sbias[tid] = __ldg(bias + tid);
    const float epc = 1.0f + __ldg(epsp);

    stage_a_f16_64(A, Ah, Al, tid, row0, M);
    cp_commit_wait();
    __syncthreads();

    const int wr0 = (warp >> 1) * 16;
    const int wc0 = (warp & 1) * 64;

    float acc[8][4];
    mma_pass16(Ah, Al, Wh, lane, wr0, wc0, acc);
    __syncthreads();

    z_to_planes16(Ah, Al, sbias, acc, lane, wr0, wc0);
    __syncthreads();
    planes_to_global64_agg(Ah, Al, oh, ol, agg, epc, tid, row0, M);
}

// ---------------- fused 2-layer MLP (64-row tile, occ 3, W reloaded) ----------------
// OUT16: writes h planes + seeds agg with next conv's eps; else fp32 out.
#define G2_SMEM (2 * HPLANE_B + PLANE_B + 1024)

template <bool OUT16>
__global__ __launch_bounds__(256, 3)
void gemm2_tc(const float* __restrict__ A,
              const float4* __restrict__ W1P, const float4* __restrict__ W2P,
              const float* __restrict__ b1, const float* __restrict__ b2,
              const float* __restrict__ epsNext,
              float* __restrict__ out, __half* __restrict__ oh, __half* __restrict__ ol,
              float* __restrict__ agg, int M)
{
    extern __shared__ char sm[];
    __half* Ah = (__half*)sm;
    __half* Al = Ah + 64 * LDP;
    __half* Wp = Al + 64 * LDP;
    float* sb1 = (float*)(sm + 2 * HPLANE_B + PLANE_B);
    float* sb2 = sb1 + 128;
    uint32_t sbW = (uint32_t)__cvta_generic_to_shared(Wp);

    const int tid = threadIdx.x;
    const int warp = tid >> 5, lane = tid & 31;
    const int row0 = blockIdx.x * 64;

#pragma unroll
    for (int i = 0; i < 9; i++) {
        int j = tid + i * 256;
        if (j < PLANE_F4) cp16(sbW + j * 16, W1P + j);
    }
    if (tid < 128) sb1[tid] = __ldg(b1 + tid);
    else           sb2[tid - 128] = __ldg(b2 + tid - 128);
    float epc = 1.0f;
    if (OUT16) epc = 1.0f + __ldg(epsNext);

    stage_a_f16_64(A, Ah, Al, tid, row0, M);
    cp_commit_wait();
    __syncthreads();

    const int wr0 = (warp >> 1) * 16;
    const int wc0 = (warp & 1) * 64;

    float acc[8][4];
    mma_pass16(Ah, Al, Wp, lane, wr0, wc0, acc);
    __syncthreads();

#pragma unroll
    for (int i = 0; i < 9; i++) {
        int j = tid + i * 256;
        if (j < PLANE_F4) cp16(sbW + j * 16, W2P + j);
    }
    z_to_planes16(Ah, Al, sb1, acc, lane, wr0, wc0);
    cp_commit_wait();
    __syncthreads();

    mma_pass16(Ah, Al, Wp, lane, wr0, wc0, acc);
    __syncthreads();

    if (OUT16) {
        z_to_planes16(Ah, Al, sb2, acc, lane, wr0, wc0);
        __syncthreads();
        planes_to_global64_agg(Ah, Al, oh, ol, agg, epc, tid, row0, M);
    } else {
        float* ftile = (float*)sm;
        const int cb = (lane & 3) * 2;
        const int rl = wr0 + (lane >> 2);
#pragma unroll
        for (int t = 0; t < 8; t++) {
            const int n = wc0 + t * 8 + cb;
            const float b0 = sb2[n], b1v = sb2[n + 1];
            float2 o0 = make_float2(fmaxf(acc[t][0] + b0, 0.f),
                                    fmaxf(acc[t][1] + b1v, 0.f));
            float2 o1 = make_float2(fmaxf(acc[t][2] + b0, 0.f),
                                    fmaxf(acc[t][3] + b1v, 0.f));
            *(float2*)(ftile + (size_t)rl * FT_PITCH + n)       = o0;
            *(float2*)(ftile + (size_t)(rl + 8) * FT_PITCH + n) = o1;
        }
        __syncthreads();
#pragma unroll
        for (int i = 0; i < 8; i++) {
            int j = tid + i * 256;
            int r = j >> 5, c = j & 31;
            int g = row0 + r;
            if (g < M) {
                float4 v = *(const float4*)(ftile + (size_t)r * FT_PITCH + c * 4);
                *(float4*)(out + (size_t)g * CH + c * 4) = v;
            }
        }
    }
}

// ---------------- launch ----------------
extern "C" void kernel_launch(void* const* d_in, const int* in_sizes, int n_in,
                              void* d_out, int out_size)
{
    const float* x     = (const float*)d_in[0];
    const void*  eidx  = d_in[1];
    const float* eattr = (const float*)d_in[2];
    const float* W_enc = (const float*)d_in[3];
    const float* b_enc = (const float*)d_in[4];
    const float* We1   = (const float*)d_in[5];
    const float* be1   = (const float*)d_in[6];
    const float* W11   = (const float*)d_in[7];
    const float* b11   = (const float*)d_in[8];
    const float* W12   = (const float*)d_in[9];
    const float* b12   = (const float*)d_in[10];
    const float* eps1  = (const float*)d_in[11];
    const float* We2   = (const float*)d_in[12];
    const float* be2   = (const float*)d_in[13];
    const float* W21   = (const float*)d_in[14];
    const float* b21   = (const float*)d_in[15];
    const float* W22   = (const float*)d_in[16];
    const float* b22   = (const float*)d_in[17];
    const float* eps2  = (const float*)d_in[18];

    const int N = in_sizes[0] / CH;
    const int E = in_sizes[2] / 16;
    float* out = (float*)d_out;

    float* aggP;
    float4* wpl;
    __half *hhP, *hlP;
    cudaGetSymbolAddress((void**)&aggP, g_agg);
    cudaGetSymbolAddress((void**)&wpl, g_wplanes);
    cudaGetSymbolAddress((void**)&hhP, g_hh);
    cudaGetSymbolAddress((void**)&hlP, g_hl);

    cudaFuncSetAttribute((const void*)gemm_tc,
                         cudaFuncAttributeMaxDynamicSharedMemorySize, G1_SMEM);
    cudaFuncSetAttribute((const void*)gemm2_tc<true>,
                         cudaFuncAttributeMaxDynamicSharedMemorySize, G2_SMEM);
    cudaFuncSetAttribute((const void*)gemm2_tc<false>,
                         cudaFuncAttributeMaxDynamicSharedMemorySize, G2_SMEM);
    cudaFuncSetAttribute((const void*)msggemm_kernel,
                         cudaFuncAttributeMaxDynamicSharedMemorySize, MG_SMEM);

    const int nb = (N + 1023) / 1024;
    const int gb = (N + 63) / 64;
    const int ge = (E + 127) / 128;

    // fork-join: CSR build on a side stream overlapped with prep + encoder GEMM
    cudaStream_t s2;
    cudaStreamCreateWithFlags(&s2, cudaStreamNonBlocking);
    cudaEvent_t evFork, evJoin;
    cudaEventCreateWithFlags(&evFork, cudaEventDisableTiming);
    cudaEventCreateWithFlags(&evJoin, cudaEventDisableTiming);

    init_kernel<<<nb, 1024>>>((const unsigned*)eidx, 2 * E, N);
    cudaEventRecord(evFork, 0);
    cudaStreamWaitEvent(s2, evFork, 0);

    convert_hist_kernel<<<(E + 255) / 256, 256, 0, s2>>>(eidx, E);
    scan1_kernel<<<nb, 1024, 0, s2>>>(N);
    scan2_kernel<<<1, 256, 0, s2>>>(nb, N, E);
    scan3_kernel<<<nb, 1024, 0, s2>>>(N);
    place_kernel<<<(E + 255) / 256, 256, 0, s2>>>(E);
    cudaEventRecord(evJoin, s2);

    prep_weights<<<(5 * 128 * LDP + 255) / 256, 256>>>(W_enc, W11, W12, W21, W22);
    gemm_tc<<<gb, 256, G1_SMEM>>>(x, wpl, b_enc, eps1, hhP, hlP, aggP, N);

    cudaStreamWaitEvent(0, evJoin, 0);

    // ---- conv1: msggemm reduces into agg (seeded with (1+eps1)*h) ----
    msggemm_kernel<<<ge, 256, MG_SMEM>>>(eattr, We1, be1, hhP, aggP, E);
    gemm2_tc<true><<<gb, 256, G2_SMEM>>>(aggP, wpl + 1 * PLANE_F4, wpl + 2 * PLANE_F4,
                                         b11, b12, eps2, nullptr, hhP, hlP, aggP, N);

    // ---- conv2 ----
    msggemm_kernel<<<ge, 256, MG_SMEM>>>(eattr, We2, be2, hhP, aggP, E);
    gemm2_tc<false><<<gb, 256, G2_SMEM>>>(aggP, wpl + 3 * PLANE_F4, wpl + 4 * PLANE_F4,
                                          b21, b22, nullptr, out, nullptr, nullptr, nullptr, N);
}

// round 16
// speedup vs baseline: 1.5170x; 1.0674x over previous
#include <cuda_runtime.h>
#include <cuda_fp16.h>
#include <cstdint>
#include <cstddef>

#define NMAX 200000
#define EMAX 600000
#define EPAD (EMAX + 128)
#define CH 128
#define LDP 136                      // padded row pitch in fp16 elems
#define EPITCH 24                    // eattr tile pitch (16 cols + pad)
#define PLANE_B (128 * LDP * 2)      // full 128-row plane bytes (W planes)
#define HPLANE_B (64 * LDP * 2)      // 64-row A/Z plane bytes
#define PLANE_F4 (PLANE_B / 16)      // 2176 float4 per full plane
#define FT_PITCH 132                 // fp32 staging pitch

// ---------------- scratch (device globals; no allocation allowed) ----------------
__device__ __half g_hh[(size_t)NMAX * CH];   // h hi plane (fp16)
__device__ float g_agg[(size_t)NMAX * CH];   // z accumulator (seeded with (1+eps)h)
__device__ int   g_src[EMAX];
__device__ int   g_dst[EMAX];
__device__ int2  g_epack[EPAD];              // (src, eid) in CSR order
__device__ int   g_pdst[EPAD];               // dst in CSR order
__device__ __half g_eah[(size_t)EPAD * 16];  // CSR-ordered eattr hi (fp16)
__device__ __half g_eal[(size_t)EPAD * 16];  // CSR-ordered eattr lo (fp16)
__device__ int   g_cnt[NMAX];
__device__ int   g_off[NMAX + 1];
__device__ int   g_cur[NMAX];
__device__ int   g_bsum[256];
__device__ int   g_bbase[256];
__device__ int   g_idx64;
__device__ float4 g_wplanes[5 * PLANE_F4];   // 5 node-weights, fp16 planes [k][n]

// ---------------- init: zero counts + edge_index dtype sniff ----------------
__global__ void init_kernel(const unsigned* __restrict__ p, int nwords, int N)
{
    __shared__ unsigned s[32];
    int gi = blockIdx.x * 1024 + threadIdx.x;
    if (gi < N) g_cnt[gi] = 0;
    if (blockIdx.x == 0) {
        unsigned v = 0;
        for (int i = threadIdx.x; i < 4096; i += 1024) {
            int w = 2 * i + 1;
            if (w < nwords) v |= p[w];
        }
#pragma unroll
        for (int o = 16; o > 0; o >>= 1) v |= __shfl_xor_sync(0xffffffffu, v, o);
        int lane = threadIdx.x & 31, wid = threadIdx.x >> 5;
        if (lane == 0) s[wid] = v;
        __syncthreads();
        if (threadIdx.x == 0) {
            unsigned r = 0;
            for (int i = 0; i < 32; i++) r |= s[i];
            g_idx64 = (r == 0) ? 1 : 0;
        }
    }
}

// ---------------- weight prep ----------------
__global__ void prep_weights(const float* __restrict__ W0, const float* __restrict__ W1,
                             const float* __restrict__ W2, const float* __restrict__ W3,
                             const float* __restrict__ W4)
{
    int idx = blockIdx.x * blockDim.x + threadIdx.x;
    if (idx >= 5 * 128 * LDP) return;
    int wi = idx / (128 * LDP);
    int e  = idx % (128 * LDP);
    int k = e / LDP, n = e % LDP;
    const float* W = (wi == 0) ? W0 : (wi == 1) ? W1 : (wi == 2) ? W2 : (wi == 3) ? W3 : W4;
    __half h = __float2half_rn(0.f);
    if (n < 128) h = __float2half_rn(__ldg(W + k * 128 + n));
    ((__half*)g_wplanes)[(size_t)wi * 128 * LDP + e] = h;
}

// ---------------- fp16 helpers ----------------
__device__ __forceinline__ uint32_t pack_h2_hi(float a, float b)
{
    __half ha = __float2half_rn(a), hb = __float2half_rn(b);
    return ((uint32_t)__half_as_ushort(hb) << 16) | __half_as_ushort(ha);
}
__device__ __forceinline__ uint32_t pack_h2_lo(float a, float b)
{
    __half ha = __float2half_rn(a), hb = __float2half_rn(b);
    __half la = __float2half_rn(a - __half2float(ha));
    __half lb = __float2half_rn(b - __half2float(hb));
    return ((uint32_t)__half_as_ushort(lb) << 16) | __half_as_ushort(la);
}
__device__ __forceinline__ void ldsm_x4(uint32_t* r, const void* p)
{
    uint32_t a = (uint32_t)__cvta_generic_to_shared(p);
    asm volatile("ldmatrix.sync.aligned.m8n8.x4.shared.b16 {%0,%1,%2,%3}, [%4];"
                 : "=r"(r[0]), "=r"(r[1]), "=r"(r[2]), "=r"(r[3]) : "r"(a));
}
__device__ __forceinline__ void ldsm_x4_t(uint32_t* r, const void* p)
{
    uint32_t a = (uint32_t)__cvta_generic_to_shared(p);
    asm volatile("ldmatrix.sync.aligned.m8n8.x4.trans.shared.b16 {%0,%1,%2,%3}, [%4];"
                 : "=r"(r[0]), "=r"(r[1]), "=r"(r[2]), "=r"(r[3]) : "r"(a));
}
__device__ __forceinline__ void mma_f16(float* c, const uint32_t* a, uint32_t b0, uint32_t b1)
{
    asm volatile("mma.sync.aligned.m16n8k16.row.col.f32.f16.f16.f32 "
                 "{%0,%1,%2,%3}, {%4,%5,%6,%7}, {%8,%9}, {%0,%1,%2,%3};"
                 : "+f"(c[0]), "+f"(c[1]), "+f"(c[2]), "+f"(c[3])
                 : "r"(a[0]), "r"(a[1]), "r"(a[2]), "r"(a[3]), "r"(b0), "r"(b1));
}
__device__ __forceinline__ void cp16(uint32_t dst, const void* src)
{
    asm volatile("cp.async.cg.shared.global [%0], [%1], 16;" :: "r"(dst), "l"(src) : "memory");
}
__device__ __forceinline__ void cp_commit_wait()
{
    asm volatile("cp.async.commit_group;\ncp.async.wait_group 0;" ::: "memory");
}
__device__ __forceinline__ void red_add4(float* gp, float4 v)
{
    size_t ga = __cvta_generic_to_global(gp);
    asm volatile("red.global.add.v4.f32 [%0], {%1,%2,%3,%4};"
                 :: "l"(ga), "f"(v.x), "f"(v.y), "f"(v.z), "f"(v.w) : "memory");
}

// ---------------- CSR build ----------------
__global__ void convert_hist_kernel(const void* __restrict__ ei, int E)
{
    int i = blockIdx.x * blockDim.x + threadIdx.x;
    if (i >= E) return;
    int s, d;
    if (g_idx64) {
        const long long* p = (const long long*)ei;
        s = (int)p[i];
        d = (int)p[(size_t)E + i];
    } else {
        const int* p = (const int*)ei;
        s = p[i];
        d = p[E + i];
    }
    g_src[i] = s;
    g_dst[i] = d;
    atomicAdd(&g_cnt[d], 1);
}

__global__ void scan1_kernel(int N)
{
    __shared__ int s[32];
    int idx = blockIdx.x * 1024 + threadIdx.x;
    int v = (idx < N) ? g_cnt[idx] : 0;
    int t = v;
#pragma unroll
    for (int o = 16; o > 0; o >>= 1) t += __shfl_xor_sync(0xffffffffu, t, o);
    if ((threadIdx.x & 31) == 0) s[threadIdx.x >> 5] = t;
    __syncthreads();
    if (threadIdx.x == 0) {
        int r = 0;
        for (int i = 0; i < 32; i++) r += s[i];
        g_bsum[blockIdx.x] = r;
    }
}

__global__ void scan2_kernel(int nb, int N, int E)
{
    __shared__ int s[256];
    int t = threadIdx.x;
    int v = (t < nb) ? g_bsum[t] : 0;
    s[t] = v;
    __syncthreads();
#pragma unroll
    for (int o = 1; o < 256; o <<= 1) {
        int nv = s[t];
        if (t >= o) nv += s[t - o];
        __syncthreads();
        s[t] = nv;
        __syncthreads();
    }
    if (t < nb) g_bbase[t] = s[t] - v;
    if (t == 0) g_off[N] = E;
}

__global__ void scan3_kernel(int N)
{
    __shared__ int s[1024];
    int idx = blockIdx.x * 1024 + threadIdx.x;
    int t = threadIdx.x;
    int v = (idx < N) ? g_cnt[idx] : 0;
    s[t] = v;
    __syncthreads();
#pragma unroll
    for (int o = 1; o < 1024; o <<= 1) {
        int nv = s[t];
        if (t >= o) nv += s[t - o];
        __syncthreads();
        s[t] = nv;
        __syncthreads();
    }
    if (idx < N) {
        int excl = g_bbase[blockIdx.x] + s[t] - v;
        g_off[idx] = excl;
        g_cur[idx] = excl;
    }
}

__global__ void place_kernel(int E)
{
    int i = blockIdx.x * blockDim.x + threadIdx.x;
    if (i >= E) return;
    int d = g_dst[i];
    int p = atomicAdd(&g_cur[d], 1);
    g_epack[p] = make_int2(g_src[i], i);
    g_pdst[p] = d;
}

// ---------------- eattr prep: gather + split into CSR-ordered fp16 planes ----------------
// 2 threads per CSR slot; runs on the overlapped side stream.
__global__ void eprep_kernel(const float* __restrict__ eattr, int E)
{
    int i = blockIdx.x * blockDim.x + threadIdx.x;
    int p = i >> 1;
    if (p >= E) return;
    int half = i & 1;
    int eid = __ldg(&g_epack[p].y);
    const float4* ea = (const float4*)eattr + (size_t)eid * 4 + half * 2;
    float4 v0 = __ldg(ea);
    float4 v1 = __ldg(ea + 1);
    size_t base = (size_t)p * 16 + half * 8;
    *(uint2*)(g_eah + base)     = make_uint2(pack_h2_hi(v0.x, v0.y), pack_h2_hi(v0.z, v0.w));
    *(uint2*)(g_eah + base + 4) = make_uint2(pack_h2_hi(v1.x, v1.y), pack_h2_hi(v1.z, v1.w));
    *(uint2*)(g_eal + base)     = make_uint2(pack_h2_lo(v0.x, v0.y), pack_h2_lo(v0.z, v0.w));
    *(uint2*)(g_eal + base + 4) = make_uint2(pack_h2_lo(v1.x, v1.y), pack_h2_lo(v1.z, v1.w));
}

// ---------------- message GEMM + in-CTA segment reduction ----------------
// msg[slot] = relu(hh[src] + eattr@We + be) built in smem; per-warp run-length
// reduction over CSR-sorted dst; partials red.add'ed into agg (pre-seeded).
#define MG_HS   (128 * LDP * 2)
#define MG_AE   (MG_HS + 2 * 128 * EPITCH * 2)
#define MG_W    (MG_AE + 2 * 16 * LDP * 2)
#define MG_SMEM (MG_W + 512 + 512 + 256)

__global__ __launch_bounds__(256, 3)
void msggemm_kernel(const float* __restrict__ We, const float* __restrict__ be,
                    const __half* __restrict__ hh, float* __restrict__ agg, int E)
{
    extern __shared__ char sm[];
    __half* Hs  = (__half*)sm;                   // [128][LDP]: h rows, then msg rows
    __half* Aeh = (__half*)(sm + MG_HS);         // [128][EPITCH]
    __half* Ael = Aeh + 128 * EPITCH;
    __half* Wh  = (__half*)(sm + MG_AE);         // [16][LDP]
    __half* Wl  = Wh + 16 * LDP;
    float* sb   = (float*)(sm + MG_W);
    int*   sdst = (int*)(sm + MG_W + 512);
    uint32_t sbH  = (uint32_t)__cvta_generic_to_shared(Hs);
    uint32_t sbAh = (uint32_t)__cvta_generic_to_shared(Aeh);
    uint32_t sbAl = (uint32_t)__cvta_generic_to_shared(Ael);

    const int tid = threadIdx.x;
    const int warp = tid >> 5, lane = tid & 31;
    const int p0 = blockIdx.x * 128;

    // gather h[src] rows via cp.async (2048 x 16B)
#pragma unroll
    for (int i = 0; i < 8; i++) {
        int j = tid + i * 256;
        int rowp = j >> 4, c = j & 15;
        int p = p0 + rowp;
        int s = (p < E) ? __ldg(&g_epack[p].x) : 0;
        cp16(sbH + rowp * (LDP * 2) + c * 16, (const char*)(hh + (size_t)s * CH) + c * 16);
    }

    // sequential cp.async of pre-split eattr tiles (hi/lo, 32B per row each)
#pragma unroll
    for (int i = 0; i < 2; i++) {
        int j = tid + i * 256;         // 0..511
        int plane = j >> 8;            // 0: hi, 1: lo
        int rowp = (j & 255) >> 1;
        int c = j & 1;
        const __half* srcp = (plane ? g_eal : g_eah) + (size_t)(p0 + rowp) * 16 + c * 8;
        uint32_t dst = (plane ? sbAl : sbAh) + rowp * (EPITCH * 2) + c * 16;
        cp16(dst, srcp);
    }

    // stage We (split) + bias + dst tags
    for (int i = tid; i < 2048; i += 256) {
        int k = i >> 7, n = i & 127;
        float v = __ldg(We + i);
        __half h = __float2half_rn(v);
        Wh[k * LDP + n] = h;
        Wl[k * LDP + n] = __float2half_rn(v - __half2float(h));
    }
    if (tid < 128) sb[tid] = __ldg(be + tid);
    else           sdst[tid - 128] = (p0 + tid - 128 < E) ? __ldg(&g_pdst[p0 + tid - 128]) : -1;
    cp_commit_wait();
    __syncthreads();

    const int wr0 = warp * 16;
    const int arow = wr0 + (lane & 15);
    const int aoff = (lane >> 4) << 3;

    uint32_t ah[4], al[4];
    ldsm_x4(ah, Aeh + arow * EPITCH + aoff);
    ldsm_x4(al, Ael + arow * EPITCH + aoff);

    const int brow = (lane & 15);
    const int cb = (lane & 3) * 2;
    const int rl0 = wr0 + (lane >> 2);

    // compute messages; overwrite Hs rows in place (each slot read+written by same thread)
#pragma unroll
    for (int nh = 0; nh < 2; nh++) {
        float acc[8][4];
#pragma unroll
        for (int t = 0; t < 8; t++)
#pragma unroll
            for (int j = 0; j < 4; j++) acc[t][j] = 0.f;
#pragma unroll
        for (int ng = 0; ng < 4; ng++) {
            const int n0 = nh * 64 + ng * 16;
            uint32_t bh[4], bl[4];
            ldsm_x4_t(bh, Wh + brow * LDP + n0 + aoff);
            ldsm_x4_t(bl, Wl + brow * LDP + n0 + aoff);
            mma_f16(acc[ng * 2],     ah, bh[0], bh[1]);
            mma_f16(acc[ng * 2],     al, bh[0], bh[1]);
            mma_f16(acc[ng * 2],     ah, bl[0], bl[1]);
            mma_f16(acc[ng * 2 + 1], ah, bh[2], bh[3]);
            mma_f16(acc[ng * 2 + 1], al, bh[2], bh[3]);
            mma_f16(acc[ng * 2 + 1], ah, bl[2], bl[3]);
        }
#pragma unroll
        for (int t = 0; t < 8; t++) {
            const int n = nh * 64 + t * 8 + cb;
            const float b0 = sb[n], b1 = sb[n + 1];
            {
                uint32_t* hp = (uint32_t*)(Hs + (size_t)rl0 * LDP + n);
                float2 hv = __half22float2(*(__half2*)hp);
                *hp = pack_h2_hi(fmaxf(hv.x + acc[t][0] + b0, 0.f),
                                 fmaxf(hv.y + acc[t][1] + b1, 0.f));
            }
            {
                uint32_t* hp = (uint32_t*)(Hs + (size_t)(rl0 + 8) * LDP + n);
                float2 hv = __half22float2(*(__half2*)hp);
                *hp = pack_h2_hi(fmaxf(hv.x + acc[t][2] + b0, 0.f),
                                 fmaxf(hv.y + acc[t][3] + b1, 0.f));
            }
        }
    }
    __syncthreads();

    // segment reduction: warp w scans slots [w*16, w*16+16); lane owns 4 channels
    {
        const int sbase = warp * 16;
        float4 racc = make_float4(0.f, 0.f, 0.f, 0.f);
        int cur = sdst[sbase];
#pragma unroll
        for (int i = 0; i < 16; i++) {
            int d = sdst[sbase + i];
            if (d != cur) {
                if (cur >= 0) red_add4(agg + (size_t)cur * CH + lane * 4, racc);
                racc = make_float4(0.f, 0.f, 0.f, 0.f);
                cur = d;
            }
            if (d >= 0) {
                uint2 mv = *(const uint2*)(Hs + (size_t)(sbase + i) * LDP + lane * 4);
                float2 f01 = __half22float2(*(__half2*)&mv.x);
                float2 f23 = __half22float2(*(__half2*)&mv.y);
                racc.x += f01.x;
                racc.y += f01.y;
                racc.z += f23.x;
                racc.w += f23.y;
            }
        }
        if (cur >= 0) red_add4(agg + (size_t)cur * CH + lane * 4, racc);
    }
}

// stage 64-row A tile (fp32 source) into fp16 hi/lo planes
__device__ __forceinline__ void stage_a_f16_64(const float* __restrict__ A,
                                               __half* Ah, __half* Al,
                                               int tid, int row0, int M)
{
#pragma unroll
    for (int i = 0; i < 8; i++) {
        int idx = tid + i * 256;
        int r = idx >> 5, c4 = idx & 31;
        int g = row0 + r;
        float4 v = make_float4(0.f, 0.f, 0.f, 0.f);
        if (g < M) v = __ldg((const float4*)(A + (size_t)g * CH) + c4);
        *(uint2*)(Ah + r * LDP + c4 * 4) = make_uint2(pack_h2_hi(v.x, v.y), pack_h2_hi(v.z, v.w));
        *(uint2*)(Al + r * LDP + c4 * 4) = make_uint2(pack_h2_lo(v.x, v.y), pack_h2_lo(v.z, v.w));
    }
}

// 2-term fp16 pass, warp tile 16 rows x 64 cols
__device__ __forceinline__ void mma_pass16(const __half* Ah, const __half* Al,
                                           const __half* Bh,
                                           int lane, int wr0, int wc0, float acc[8][4])
{
#pragma unroll
    for (int t = 0; t < 8; t++)
#pragma unroll
        for (int j = 0; j < 4; j++) acc[t][j] = 0.f;

    const int arow = wr0 + (lane & 15);
    const int aoff = (lane >> 4) << 3;

#pragma unroll
    for (int kc = 0; kc < 8; kc++) {
        const int kb = kc * 16;
        uint32_t ah[4], al[4];
        ldsm_x4(ah, Ah + (size_t)arow * LDP + kb + aoff);
        ldsm_x4(al, Al + (size_t)arow * LDP + kb + aoff);
        const int brow = kb + (lane & 15);
#pragma unroll
        for (int ng = 0; ng < 4; ng++) {
            uint32_t b[4];
            ldsm_x4_t(b, Bh + (size_t)brow * LDP + wc0 + ng * 16 + aoff);
            mma_f16(acc[ng * 2],     ah, b[0], b[1]);
            mma_f16(acc[ng * 2],     al, b[0], b[1]);
            mma_f16(acc[ng * 2 + 1], ah, b[2], b[3]);
            mma_f16(acc[ng * 2 + 1], al, b[2], b[3]);
        }
    }
}

__device__ __forceinline__ void z_to_planes16(__half* Ah, __half* Al, const float* sb,
                                              float acc[8][4], int lane, int wr0, int wc0)
{
    const int cb = (lane & 3) * 2;
    const int rl = wr0 + (lane >> 2);
#pragma unroll
    for (int t = 0; t < 8; t++) {
        const int n = wc0 + t * 8 + cb;
        const float b0 = sb[n], b1v = sb[n + 1];
        float z0 = fmaxf(acc[t][0] + b0, 0.f);
        float z1 = fmaxf(acc[t][1] + b1v, 0.f);
        float z2 = fmaxf(acc[t][2] + b0, 0.f);
        float z3 = fmaxf(acc[t][3] + b1v, 0.f);
        *(uint32_t*)(Ah + (size_t)rl * LDP + n)       = pack_h2_hi(z0, z1);
        *(uint32_t*)(Al + (size_t)rl * LDP + n)       = pack_h2_lo(z0, z1);
        *(uint32_t*)(Ah + (size_t)(rl + 8) * LDP + n) = pack_h2_hi(z2, z3);
        *(uint32_t*)(Al + (size_t)(rl + 8) * LDP + n) = pack_h2_lo(z2, z3);
    }
}

// copy hi plane to global + seed agg = epc * (hi + lo); NO lo store (dead)
__device__ __forceinline__ void planes_to_global64_agg(const __half* Ah, const __half* Al,
                                                       __half* oh, float* agg, float epc,
                                                       int tid, int row0, int M)
{
#pragma unroll
    for (int i = 0; i < 4; i++) {
        int j = tid + i * 256;
        int r = j >> 4, c = j & 15;
        int g = row0 + r;
        if (g < M) {
            uint4 vh = *(const uint4*)((const char*)Ah + (size_t)r * LDP * 2 + c * 16);
            uint4 vl = *(const uint4*)((const char*)Al + (size_t)r * LDP * 2 + c * 16);
            *(uint4*)((char*)(oh + (size_t)g * CH) + c * 16) = vh;
            float2 a0 = __half22float2(*(__half2*)&vh.x);
            float2 a1 = __half22float2(*(__half2*)&vh.y);
            float2 a2 = __half22float2(*(__half2*)&vh.z);
            float2 a3 = __half22float2(*(__half2*)&vh.w);
            float2 b0 = __half22float2(*(__half2*)&vl.x);
            float2 b1 = __half22float2(*(__half2*)&vl.y);
            float2 b2 = __half22float2(*(__half2*)&vl.z);
            float2 b3 = __half22float2(*(__half2*)&vl.w);
            float* ap = agg + (size_t)g * CH + c * 8;
            *(float4*)ap = make_float4(epc * (a0.x + b0.x), epc * (a0.y + b0.y),
                                       epc * (a1.x + b1.x), epc * (a1.y + b1.y));
            *(float4*)(ap + 4) = make_float4(epc * (a2.x + b2.x), epc * (a2.y + b2.y),
                                             epc * (a3.x + b3.x), epc * (a3.y + b3.y));
        }
    }
}

// ---------------- encoder GEMM (64-row tile, occ 3): writes h hi plane + agg seed ----------------
#define G1_SMEM (2 * HPLANE_B + PLANE_B + 512)

__global__ __launch_bounds__(256, 3)
void gemm_tc(const float* __restrict__ A, const float4* __restrict__ WhP,
             const float* __restrict__ bias, const float* __restrict__ epsp,
             __half* __restrict__ oh, float* __restrict__ agg, int M)
{
    extern __shared__ char sm[];
    __half* Ah = (__half*)sm;
    __half* Al = Ah + 64 * LDP;
    __half* Wh = Al + 64 * LDP;
    float* sbias = (float*)(sm + 2 * HPLANE_B + PLANE_B);
    uint32_t sbW = (uint32_t)__cvta_generic_to_shared(Wh);

    const int tid = threadIdx.x;
    const int warp = tid >> 5, lane = tid & 31;
    const int row0 = blockIdx.x * 64;

#pragma unroll
    for (int i = 0; i < 9; i++) {
        int j = tid + i * 256;
        if (j < PLANE_F4) cp16(sbW + j * 16, WhP + j);
    }
    if (tid < 128) sbias[tid] = __ldg(bias + tid);
    const float epc = 1.0f + __ldg(epsp);

    stage_a_f16_64(A, Ah, Al, tid, row0, M);
    cp_commit_wait();
    __syncthreads();

    const int wr0 = (warp >> 1) * 16;
    const int wc0 = (warp & 1) * 64;

    float acc[8][4];
    mma_pass16(Ah, Al, Wh, lane, wr0, wc0, acc);
    __syncthreads();

    z_to_planes16(Ah, Al, sbias, acc, lane, wr0, wc0);
    __syncthreads();
    planes_to_global64_agg(Ah, Al, oh, agg, epc, tid, row0, M);
}

// ---------------- fused 2-layer MLP (64-row tile, occ 3, W reloaded) ----------------
#define G2_SMEM (2 * HPLANE_B + PLANE_B + 1024)

template <bool OUT16>
__global__ __launch_bounds__(256, 3)
void gemm2_tc(const float* __restrict__ A,
              const float4* __restrict__ W1P, const float4* __restrict__ W2P,
              const float* __restrict__ b1, const float* __restrict__ b2,
              const float* __restrict__ epsNext,
              float* __restrict__ out, __half* __restrict__ oh,
              float* __restrict__ agg, int M)
{
    extern __shared__ char sm[];
    __half* Ah = (__half*)sm;
    __half* Al = Ah + 64 * LDP;
    __half* Wp = Al + 64 * LDP;
    float* sb1 = (float*)(sm + 2 * HPLANE_B + PLANE_B);
    float* sb2 = sb1 + 128;
    uint32_t sbW = (uint32_t)__cvta_generic_to_shared(Wp);

    const int tid = threadIdx.x;
    const int warp = tid >> 5, lane = tid & 31;
    const int row0 = blockIdx.x * 64;

#pragma unroll
    for (int i = 0; i < 9; i++) {
        int j = tid + i * 256;
        if (j < PLANE_F4) cp16(sbW + j * 16, W1P + j);
    }
    if (tid < 128) sb1[tid] = __ldg(b1 + tid);
    else           sb2[tid - 128] = __ldg(b2 + tid - 128);
    float epc = 1.0f;
    if (OUT16) epc = 1.0f + __ldg(epsNext);

    stage_a_f16_64(A, Ah, Al, tid, row0, M);
    cp_commit_wait();
    __syncthreads();

    const int wr0 = (warp >> 1) * 16;
    const int wc0 = (warp & 1) * 64;

    float acc[8][4];
    mma_pass16(Ah, Al, Wp, lane, wr0, wc0, acc);
    __syncthreads();

#pragma unroll
    for (int i = 0; i < 9; i++) {
        int j = tid + i * 256;
        if (j < PLANE_F4) cp16(sbW + j * 16, W2P + j);
    }
    z_to_planes16(Ah, Al, sb1, acc, lane, wr0, wc0);
    cp_commit_wait();
    __syncthreads();

    mma_pass16(Ah, Al, Wp, lane, wr0, wc0, acc);
    __syncthreads();

    if (OUT16) {
        z_to_planes16(Ah, Al, sb2, acc, lane, wr0, wc0);
        __syncthreads();
        planes_to_global64_agg(Ah, Al, oh, agg, epc, tid, row0, M);
    } else {
        float* ftile = (float*)sm;
        const int cb = (lane & 3) * 2;
        const int rl = wr0 + (lane >> 2);
#pragma unroll
        for (int t = 0; t < 8; t++) {
            const int n = wc0 + t * 8 + cb;
            const float b0 = sb2[n], b1v = sb2[n + 1];
            float2 o0 = make_float2(fmaxf(acc[t][0] + b0, 0.f),
                                    fmaxf(acc[t][1] + b1v, 0.f));
            float2 o1 = make_float2(fmaxf(acc[t][2] + b0, 0.f),
                                    fmaxf(acc[t][3] + b1v, 0.f));
            *(float2*)(ftile + (size_t)rl * FT_PITCH + n)       = o0;
            *(float2*)(ftile + (size_t)(rl + 8) * FT_PITCH + n) = o1;
        }
        __syncthreads();
#pragma unroll
        for (int i = 0; i < 8; i++) {
            int j = tid + i * 256;
            int r = j >> 5, c = j & 31;
            int g = row0 + r;
            if (g < M) {
                float4 v = *(const float4*)(ftile + (size_t)r * FT_PITCH + c * 4);
                *(float4*)(out + (size_t)g * CH + c * 4) = v;
            }
        }
    }
}

// ---------------- launch ----------------
extern "C" void kernel_launch(void* const* d_in, const int* in_sizes, int n_in,
                              void* d_out, int out_size)
{
    const float* x     = (const float*)d_in[0];
    const void*  eidx  = d_in[1];
    const float* eattr = (const float*)d_in[2];
    const float* W_enc = (const float*)d_in[3];
    const float* b_enc = (const float*)d_in[4];
    const float* We1   = (const float*)d_in[5];
    const float* be1   = (const float*)d_in[6];
    const float* W11   = (const float*)d_in[7];
    const float* b11   = (const float*)d_in[8];
    const float* W12   = (const float*)d_in[9];
    const float* b12   = (const float*)d_in[10];
    const float* eps1  = (const float*)d_in[11];
    const float* We2   = (const float*)d_in[12];
    const float* be2   = (const float*)d_in[13];
    const float* W21   = (const float*)d_in[14];
    const float* b21   = (const float*)d_in[15];
    const float* W22   = (const float*)d_in[16];
    const float* b22   = (const float*)d_in[17];
    const float* eps2  = (const float*)d_in[18];

    const int N = in_sizes[0] / CH;
    const int E = in_sizes[2] / 16;
    float* out = (float*)d_out;

    float* aggP;
    float4* wpl;
    __half* hhP;
    cudaGetSymbolAddress((void**)&aggP, g_agg);
    cudaGetSymbolAddress((void**)&wpl, g_wplanes);
    cudaGetSymbolAddress((void**)&hhP, g_hh);

    cudaFuncSetAttribute((const void*)gemm_tc,
                         cudaFuncAttributeMaxDynamicSharedMemorySize, G1_SMEM);
    cudaFuncSetAttribute((const void*)gemm2_tc<true>,
                         cudaFuncAttributeMaxDynamicSharedMemorySize, G2_SMEM);
    cudaFuncSetAttribute((const void*)gemm2_tc<false>,
                         cudaFuncAttributeMaxDynamicSharedMemorySize, G2_SMEM);
    cudaFuncSetAttribute((const void*)msggemm_kernel,
                         cudaFuncAttributeMaxDynamicSharedMemorySize, MG_SMEM);

    const int nb = (N + 1023) / 1024;
    const int gb = (N + 63) / 64;
    const int ge = (E + 127) / 128;

    // fork-join: CSR build + eattr prep on a side stream overlapped with
    // weight prep + encoder GEMM on the main (capture) stream.
    cudaStream_t s2;
    cudaStreamCreateWithFlags(&s2, cudaStreamNonBlocking);
    cudaEvent_t evFork, evJoin;
    cudaEventCreateWithFlags(&evFork, cudaEventDisableTiming);
    cudaEventCreateWithFlags(&evJoin, cudaEventDisableTiming);

    init_kernel<<<nb, 1024>>>((const unsigned*)eidx, 2 * E, N);
    cudaEventRecord(evFork, 0);
    cudaStreamWaitEvent(s2, evFork, 0);

    convert_hist_kernel<<<(E + 255) / 256, 256, 0, s2>>>(eidx, E);
    scan1_kernel<<<nb, 1024, 0, s2>>>(N);
    scan2_kernel<<<1, 256, 0, s2>>>(nb, N, E);
    scan3_kernel<<<nb, 1024, 0, s2>>>(N);
    place_kernel<<<(E + 255) / 256, 256, 0, s2>>>(E);
    eprep_kernel<<<(2 * E + 255) / 256, 256, 0, s2>>>(eattr, E);
    cudaEventRecord(evJoin, s2);

    prep_weights<<<(5 * 128 * LDP + 255) / 256, 256>>>(W_enc, W11, W12, W21, W22);
    gemm_tc<<<gb, 256, G1_SMEM>>>(x, wpl, b_enc, eps1, hhP, aggP, N);

    cudaStreamWaitEvent(0, evJoin, 0);

    // ---- conv1 ----
    msggemm_kernel<<<ge, 256, MG_SMEM>>>(We1, be1, hhP, aggP, E);
    gemm2_tc<true><<<gb, 256, G2_SMEM>>>(aggP, wpl + 1 * PLANE_F4, wpl + 2 * PLANE_F4,
                                         b11, b12, eps2, nullptr, hhP, aggP, N);

    // ---- conv2 ----
    msggemm_kernel<<<ge, 256, MG_SMEM>>>(We2, be2, hhP, aggP, E);
    gemm2_tc<false><<<gb, 256, G2_SMEM>>>(aggP, wpl + 3 * PLANE_F4, wpl + 4 * PLANE_F4,
                                          b21, b22, nullptr, out, nullptr, nullptr, N);
}

// round 17
// speedup vs baseline: 1.7686x; 1.1659x over previous
#include <cuda_runtime.h>
#include <cuda_fp16.h>
#include <cstdint>
#include <cstddef>

#define NMAX 200000
#define EMAX 600000
#define EPAD (EMAX + 128)
#define CH 128
#define LDP 136                      // padded row pitch in fp16 elems
#define EPITCH 24                    // eattr tile pitch (16 cols + pad)
#define PLANE_B (128 * LDP * 2)      // full 128-row plane bytes (W planes)
#define HPLANE_B (64 * LDP * 2)      // 64-row A/Z plane bytes
#define PLANE_F4 (PLANE_B / 16)      // 2176 float4 per full plane
#define FT_PITCH 132                 // fp32 staging pitch

// ---------------- scratch (device globals; no allocation allowed) ----------------
__device__ __half g_hh[(size_t)NMAX * CH];   // h hi plane (fp16)
__device__ __half g_agg[(size_t)NMAX * CH];  // z accumulator, fp16 (seeded with (1+eps)h)
__device__ int   g_src[EMAX];
__device__ int   g_dst[EMAX];
__device__ int2  g_epack[EPAD];              // (src, eid) in CSR order
__device__ int   g_pdst[EPAD];               // dst in CSR order
__device__ __half g_eah[(size_t)EPAD * 16];  // CSR-ordered eattr hi (fp16)
__device__ __half g_eal[(size_t)EPAD * 16];  // CSR-ordered eattr lo (fp16)
__device__ int   g_cnt[NMAX];
__device__ int   g_off[NMAX + 1];
__device__ int   g_cur[NMAX];
__device__ int   g_bsum[256];
__device__ int   g_bbase[256];
__device__ int   g_idx64;
__device__ float4 g_wplanes[5 * PLANE_F4];   // 5 node-weights, fp16 planes [k][n]

// ---------------- init: zero counts + edge_index dtype sniff ----------------
__global__ void init_kernel(const unsigned* __restrict__ p, int nwords, int N)
{
    __shared__ unsigned s[32];
    int gi = blockIdx.x * 1024 + threadIdx.x;
    if (gi < N) g_cnt[gi] = 0;
    if (blockIdx.x == 0) {
        unsigned v = 0;
        for (int i = threadIdx.x; i < 4096; i += 1024) {
            int w = 2 * i + 1;
            if (w < nwords) v |= p[w];
        }
#pragma unroll
        for (int o = 16; o > 0; o >>= 1) v |= __shfl_xor_sync(0xffffffffu, v, o);
        int lane = threadIdx.x & 31, wid = threadIdx.x >> 5;
        if (lane == 0) s[wid] = v;
        __syncthreads();
        if (threadIdx.x == 0) {
            unsigned r = 0;
            for (int i = 0; i < 32; i++) r |= s[i];
            g_idx64 = (r == 0) ? 1 : 0;
        }
    }
}

// ---------------- weight prep ----------------
__global__ void prep_weights(const float* __restrict__ W0, const float* __restrict__ W1,
                             const float* __restrict__ W2, const float* __restrict__ W3,
                             const float* __restrict__ W4)
{
    int idx = blockIdx.x * blockDim.x + threadIdx.x;
    if (idx >= 5 * 128 * LDP) return;
    int wi = idx / (128 * LDP);
    int e  = idx % (128 * LDP);
    int k = e / LDP, n = e % LDP;
    const float* W = (wi == 0) ? W0 : (wi == 1) ? W1 : (wi == 2) ? W2 : (wi == 3) ? W3 : W4;
    __half h = __float2half_rn(0.f);
    if (n < 128) h = __float2half_rn(__ldg(W + k * 128 + n));
    ((__half*)g_wplanes)[(size_t)wi * 128 * LDP + e] = h;
}

// ---------------- fp16 helpers ----------------
__device__ __forceinline__ uint32_t pack_h2_hi(float a, float b)
{
    __half ha = __float2half_rn(a), hb = __float2half_rn(b);
    return ((uint32_t)__half_as_ushort(hb) << 16) | __half_as_ushort(ha);
}
__device__ __forceinline__ uint32_t pack_h2_lo(float a, float b)
{
    __half ha = __float2half_rn(a), hb = __float2half_rn(b);
    __half la = __float2half_rn(a - __half2float(ha));
    __half lb = __float2half_rn(b - __half2float(hb));
    return ((uint32_t)__half_as_ushort(lb) << 16) | __half_as_ushort(la);
}
__device__ __forceinline__ void ldsm_x4(uint32_t* r, const void* p)
{
    uint32_t a = (uint32_t)__cvta_generic_to_shared(p);
    asm volatile("ldmatrix.sync.aligned.m8n8.x4.shared.b16 {%0,%1,%2,%3}, [%4];"
                 : "=r"(r[0]), "=r"(r[1]), "=r"(r[2]), "=r"(r[3]) : "r"(a));
}
__device__ __forceinline__ void ldsm_x4_t(uint32_t* r, const void* p)
{
    uint32_t a = (uint32_t)__cvta_generic_to_shared(p);
    asm volatile("ldmatrix.sync.aligned.m8n8.x4.trans.shared.b16 {%0,%1,%2,%3}, [%4];"
                 : "=r"(r[0]), "=r"(r[1]), "=r"(r[2]), "=r"(r[3]) : "r"(a));
}
__device__ __forceinline__ void mma_f16(float* c, const uint32_t* a, uint32_t b0, uint32_t b1)
{
    asm volatile("mma.sync.aligned.m16n8k16.row.col.f32.f16.f16.f32 "
                 "{%0,%1,%2,%3}, {%4,%5,%6,%7}, {%8,%9}, {%0,%1,%2,%3};"
                 : "+f"(c[0]), "+f"(c[1]), "+f"(c[2]), "+f"(c[3])
                 : "r"(a[0]), "r"(a[1]), "r"(a[2]), "r"(a[3]), "r"(b0), "r"(b1));
}
__device__ __forceinline__ void cp16(uint32_t dst, const void* src)
{
    asm volatile("cp.async.cg.shared.global [%0], [%1], 16;" :: "r"(dst), "l"(src) : "memory");
}
__device__ __forceinline__ void cp_commit_wait()
{
    asm volatile("cp.async.commit_group;\ncp.async.wait_group 0;" ::: "memory");
}
// fp16x2 vector atomic add (8 bytes, one op)
__device__ __forceinline__ void red_addh4(__half* gp, float4 v)
{
    uint32_t p0 = pack_h2_hi(v.x, v.y);
    uint32_t p1 = pack_h2_hi(v.z, v.w);
    size_t ga = __cvta_generic_to_global(gp);
    asm volatile("red.global.add.noftz.v2.f16x2 [%0], {%1,%2};"
                 :: "l"(ga), "r"(p0), "r"(p1) : "memory");
}

// ---------------- CSR build ----------------
__global__ void convert_hist_kernel(const void* __restrict__ ei, int E)
{
    int i = blockIdx.x * blockDim.x + threadIdx.x;
    if (i >= E) return;
    int s, d;
    if (g_idx64) {
        const long long* p = (const long long*)ei;
        s = (int)p[i];
        d = (int)p[(size_t)E + i];
    } else {
        const int* p = (const int*)ei;
        s = p[i];
        d = p[E + i];
    }
    g_src[i] = s;
    g_dst[i] = d;
    atomicAdd(&g_cnt[d], 1);
}

__global__ void scan1_kernel(int N)
{
    __shared__ int s[32];
    int idx = blockIdx.x * 1024 + threadIdx.x;
    int v = (idx < N) ? g_cnt[idx] : 0;
    int t = v;
#pragma unroll
    for (int o = 16; o > 0; o >>= 1) t += __shfl_xor_sync(0xffffffffu, t, o);
    if ((threadIdx.x & 31) == 0) s[threadIdx.x >> 5] = t;
    __syncthreads();
    if (threadIdx.x == 0) {
        int r = 0;
        for (int i = 0; i < 32; i++) r += s[i];
        g_bsum[blockIdx.x] = r;
    }
}

__global__ void scan2_kernel(int nb, int N, int E)
{
    __shared__ int s[256];
    int t = threadIdx.x;
    int v = (t < nb) ? g_bsum[t] : 0;
    s[t] = v;
    __syncthreads();
#pragma unroll
    for (int o = 1; o < 256; o <<= 1) {
        int nv = s[t];
        if (t >= o) nv += s[t - o];
        __syncthreads();
        s[t] = nv;
        __syncthreads();
    }
    if (t < nb) g_bbase[t] = s[t] - v;
    if (t == 0) g_off[N] = E;
}

__global__ void scan3_kernel(int N)
{
    __shared__ int s[1024];
    int idx = blockIdx.x * 1024 + threadIdx.x;
    int t = threadIdx.x;
    int v = (idx < N) ? g_cnt[idx] : 0;
    s[t] = v;
    __syncthreads();
#pragma unroll
    for (int o = 1; o < 1024; o <<= 1) {
        int nv = s[t];
        if (t >= o) nv += s[t - o];
        __syncthreads();
        s[t] = nv;
        __syncthreads();
    }
    if (idx < N) {
        int excl = g_bbase[blockIdx.x] + s[t] - v;
        g_off[idx] = excl;
        g_cur[idx] = excl;
    }
}

__global__ void place_kernel(int E)
{
    int i = blockIdx.x * blockDim.x + threadIdx.x;
    if (i >= E) return;
    int d = g_dst[i];
    int p = atomicAdd(&g_cur[d], 1);
    g_epack[p] = make_int2(g_src[i], i);
    g_pdst[p] = d;
}

// ---------------- eattr prep: gather + split into CSR-ordered fp16 planes ----------------
__global__ void eprep_kernel(const float* __restrict__ eattr, int E)
{
    int i = blockIdx.x * blockDim.x + threadIdx.x;
    int p = i >> 1;
    if (p >= E) return;
    int half = i & 1;
    int eid = __ldg(&g_epack[p].y);
    const float4* ea = (const float4*)eattr + (size_t)eid * 4 + half * 2;
    float4 v0 = __ldg(ea);
    float4 v1 = __ldg(ea + 1);
    size_t base = (size_t)p * 16 + half * 8;
    *(uint2*)(g_eah + base)     = make_uint2(pack_h2_hi(v0.x, v0.y), pack_h2_hi(v0.z, v0.w));
    *(uint2*)(g_eah + base + 4) = make_uint2(pack_h2_hi(v1.x, v1.y), pack_h2_hi(v1.z, v1.w));
    *(uint2*)(g_eal + base)     = make_uint2(pack_h2_lo(v0.x, v0.y), pack_h2_lo(v0.z, v0.w));
    *(uint2*)(g_eal + base + 4) = make_uint2(pack_h2_lo(v1.x, v1.y), pack_h2_lo(v1.z, v1.w));
}

// ---------------- message GEMM + in-CTA segment reduction (fp16 atomics) ----------------
#define MG_HS   (128 * LDP * 2)
#define MG_AE   (MG_HS + 2 * 128 * EPITCH * 2)
#define MG_W    (MG_AE + 2 * 16 * LDP * 2)
#define MG_SMEM (MG_W + 512 + 512 + 256)

__global__ __launch_bounds__(256, 3)
void msggemm_kernel(const float* __restrict__ We, const float* __restrict__ be,
                    const __half* __restrict__ hh, __half* __restrict__ agg, int E)
{
    extern __shared__ char sm[];
    __half* Hs  = (__half*)sm;                   // [128][LDP]: h rows, then msg rows
    __half* Aeh = (__half*)(sm + MG_HS);         // [128][EPITCH]
    __half* Ael = Aeh + 128 * EPITCH;
    __half* Wh  = (__half*)(sm + MG_AE);         // [16][LDP]
    __half* Wl  = Wh + 16 * LDP;
    float* sb   = (float*)(sm + MG_W);
    int*   sdst = (int*)(sm + MG_W + 512);
    uint32_t sbH  = (uint32_t)__cvta_generic_to_shared(Hs);
    uint32_t sbAh = (uint32_t)__cvta_generic_to_shared(Aeh);
    uint32_t sbAl = (uint32_t)__cvta_generic_to_shared(Ael);

    const int tid = threadIdx.x;
    const int warp = tid >> 5, lane = tid & 31;
    const int p0 = blockIdx.x * 128;

    // gather h[src] rows via cp.async (2048 x 16B)
#pragma unroll
    for (int i = 0; i < 8; i++) {
        int j = tid + i * 256;
        int rowp = j >> 4, c = j & 15;
        int p = p0 + rowp;
        int s = (p < E) ? __ldg(&g_epack[p].x) : 0;
        cp16(sbH + rowp * (LDP * 2) + c * 16, (const char*)(hh + (size_t)s * CH) + c * 16);
    }

    // sequential cp.async of pre-split eattr tiles
#pragma unroll
    for (int i = 0; i < 2; i++) {
        int j = tid + i * 256;
        int plane = j >> 8;
        int rowp = (j & 255) >> 1;
        int c = j & 1;
        const __half* srcp = (plane ? g_eal : g_eah) + (size_t)(p0 + rowp) * 16 + c * 8;
        uint32_t dst = (plane ? sbAl : sbAh) + rowp * (EPITCH * 2) + c * 16;
        cp16(dst, srcp);
    }

    // stage We (split) + bias + dst tags
    for (int i = tid; i < 2048; i += 256) {
        int k = i >> 7, n = i & 127;
        float v = __ldg(We + i);
        __half h = __float2half_rn(v);
        Wh[k * LDP + n] = h;
        Wl[k * LDP + n] = __float2half_rn(v - __half2float(h));
    }
    if (tid < 128) sb[tid] = __ldg(be + tid);
    else           sdst[tid - 128] = (p0 + tid - 128 < E) ? __ldg(&g_pdst[p0 + tid - 128]) : -1;
    cp_commit_wait();
    __syncthreads();

    const int wr0 = warp * 16;
    const int arow = wr0 + (lane & 15);
    const int aoff = (lane >> 4) << 3;

    uint32_t ah[4], al[4];
    ldsm_x4(ah, Aeh + arow * EPITCH + aoff);
    ldsm_x4(al, Ael + arow * EPITCH + aoff);

    const int brow = (lane & 15);
    const int cb = (lane & 3) * 2;
    const int rl0 = wr0 + (lane >> 2);

    // compute messages; overwrite Hs rows in place
#pragma unroll
    for (int nh = 0; nh < 2; nh++) {
        float acc[8][4];
#pragma unroll
        for (int t = 0; t < 8; t++)
#pragma unroll
            for (int j = 0; j < 4; j++) acc[t][j] = 0.f;
#pragma unroll
        for (int ng = 0; ng < 4; ng++) {
            const int n0 = nh * 64 + ng * 16;
            uint32_t bh[4], bl[4];
            ldsm_x4_t(bh, Wh + brow * LDP + n0 + aoff);
            ldsm_x4_t(bl, Wl + brow * LDP + n0 + aoff);
            mma_f16(acc[ng * 2],     ah, bh[0], bh[1]);
            mma_f16(acc[ng * 2],     al, bh[0], bh[1]);
            mma_f16(acc[ng * 2],     ah, bl[0], bl[1]);
            mma_f16(acc[ng * 2 + 1], ah, bh[2], bh[3]);
            mma_f16(acc[ng * 2 + 1], al, bh[2], bh[3]);
            mma_f16(acc[ng * 2 + 1], ah, bl[2], bl[3]);
        }
#pragma unroll
        for (int t = 0; t < 8; t++) {
            const int n = nh * 64 + t * 8 + cb;
            const float b0 = sb[n], b1 = sb[n + 1];
            {
                uint32_t* hp = (uint32_t*)(Hs + (size_t)rl0 * LDP + n);
                float2 hv = __half22float2(*(__half2*)hp);
                *hp = pack_h2_hi(fmaxf(hv.x + acc[t][0] + b0, 0.f),
                                 fmaxf(hv.y + acc[t][1] + b1, 0.f));
            }
            {
                uint32_t* hp = (uint32_t*)(Hs + (size_t)(rl0 + 8) * LDP + n);
                float2 hv = __half22float2(*(__half2*)hp);
                *hp = pack_h2_hi(fmaxf(hv.x + acc[t][2] + b0, 0.f),
                                 fmaxf(hv.y + acc[t][3] + b1, 0.f));
            }
        }
    }
    __syncthreads();

    // segment reduction: warp w scans slots [w*16, w*16+16); lane owns 4 channels
    {
        const int sbase = warp * 16;
        float4 racc = make_float4(0.f, 0.f, 0.f, 0.f);
        int cur = sdst[sbase];
#pragma unroll
        for (int i = 0; i < 16; i++) {
            int d = sdst[sbase + i];
            if (d != cur) {
                if (cur >= 0) red_addh4(agg + (size_t)cur * CH + lane * 4, racc);
                racc = make_float4(0.f, 0.f, 0.f, 0.f);
                cur = d;
            }
            if (d >= 0) {
                uint2 mv = *(const uint2*)(Hs + (size_t)(sbase + i) * LDP + lane * 4);
                float2 f01 = __half22float2(*(__half2*)&mv.x);
                float2 f23 = __half22float2(*(__half2*)&mv.y);
                racc.x += f01.x;
                racc.y += f01.y;
                racc.z += f23.x;
                racc.w += f23.y;
            }
        }
        if (cur >= 0) red_addh4(agg + (size_t)cur * CH + lane * 4, racc);
    }
}

// stage 64-row A tile (fp32 source) into fp16 hi/lo planes
__device__ __forceinline__ void stage_a_f16_64(const float* __restrict__ A,
                                               __half* Ah, __half* Al,
                                               int tid, int row0, int M)
{
#pragma unroll
    for (int i = 0; i < 8; i++) {
        int idx = tid + i * 256;
        int r = idx >> 5, c4 = idx & 31;
        int g = row0 + r;
        float4 v = make_float4(0.f, 0.f, 0.f, 0.f);
        if (g < M) v = __ldg((const float4*)(A + (size_t)g * CH) + c4);
        *(uint2*)(Ah + r * LDP + c4 * 4) = make_uint2(pack_h2_hi(v.x, v.y), pack_h2_hi(v.z, v.w));
        *(uint2*)(Al + r * LDP + c4 * 4) = make_uint2(pack_h2_lo(v.x, v.y), pack_h2_lo(v.z, v.w));
    }
}

// 2-term fp16 pass, warp tile 16 rows x 64 cols
__device__ __forceinline__ void mma_pass16(const __half* Ah, const __half* Al,
                                           const __half* Bh,
                                           int lane, int wr0, int wc0, float acc[8][4])
{
#pragma unroll
    for (int t = 0; t < 8; t++)
#pragma unroll
        for (int j = 0; j < 4; j++) acc[t][j] = 0.f;

    const int arow = wr0 + (lane & 15);
    const int aoff = (lane >> 4) << 3;

#pragma unroll
    for (int kc = 0; kc < 8; kc++) {
        const int kb = kc * 16;
        uint32_t ah[4], al[4];
        ldsm_x4(ah, Ah + (size_t)arow * LDP + kb + aoff);
        ldsm_x4(al, Al + (size_t)arow * LDP + kb + aoff);
        const int brow = kb + (lane & 15);
#pragma unroll
        for (int ng = 0; ng < 4; ng++) {
            uint32_t b[4];
            ldsm_x4_t(b, Bh + (size_t)brow * LDP + wc0 + ng * 16 + aoff);
            mma_f16(acc[ng * 2],     ah, b[0], b[1]);
            mma_f16(acc[ng * 2],     al, b[0], b[1]);
            mma_f16(acc[ng * 2 + 1], ah, b[2], b[3]);
            mma_f16(acc[ng * 2 + 1], al, b[2], b[3]);
        }
    }
}

// 1-term fp16 pass (A fp16-only), warp tile 16 rows x 64 cols
__device__ __forceinline__ void mma_pass16_1t(const __half* Ah, const __half* Bh,
                                              int lane, int wr0, int wc0, float acc[8][4])
{
#pragma unroll
    for (int t = 0; t < 8; t++)
#pragma unroll
        for (int j = 0; j < 4; j++) acc[t][j] = 0.f;

    const int arow = wr0 + (lane & 15);
    const int aoff = (lane >> 4) << 3;

#pragma unroll
    for (int kc = 0; kc < 8; kc++) {
        const int kb = kc * 16;
        uint32_t ah[4];
        ldsm_x4(ah, Ah + (size_t)arow * LDP + kb + aoff);
        const int brow = kb + (lane & 15);
#pragma unroll
        for (int ng = 0; ng < 4; ng++) {
            uint32_t b[4];
            ldsm_x4_t(b, Bh + (size_t)brow * LDP + wc0 + ng * 16 + aoff);
            mma_f16(acc[ng * 2],     ah, b[0], b[1]);
            mma_f16(acc[ng * 2 + 1], ah, b[2], b[3]);
        }
    }
}

__device__ __forceinline__ void z_to_planes16(__half* Ah, __half* Al, const float* sb,
                                              float acc[8][4], int lane, int wr0, int wc0)
{
    const int cb = (lane & 3) * 2;
    const int rl = wr0 + (lane >> 2);
#pragma unroll
    for (int t = 0; t < 8; t++) {
        const int n = wc0 + t * 8 + cb;
        const float b0 = sb[n], b1v = sb[n + 1];
        float z0 = fmaxf(acc[t][0] + b0, 0.f);
        float z1 = fmaxf(acc[t][1] + b1v, 0.f);
        float z2 = fmaxf(acc[t][2] + b0, 0.f);
        float z3 = fmaxf(acc[t][3] + b1v, 0.f);
        *(uint32_t*)(Ah + (size_t)rl * LDP + n)       = pack_h2_hi(z0, z1);
        *(uint32_t*)(Al + (size_t)rl * LDP + n)       = pack_h2_lo(z0, z1);
        *(uint32_t*)(Ah + (size_t)(rl + 8) * LDP + n) = pack_h2_hi(z2, z3);
        *(uint32_t*)(Al + (size_t)(rl + 8) * LDP + n) = pack_h2_lo(z2, z3);
    }
}

// copy hi plane to global + seed agg = fp16(epc * (hi + lo))
__device__ __forceinline__ void planes_to_global64_agg(const __half* Ah, const __half* Al,
                                                       __half* oh, __half* agg, float epc,
                                                       int tid, int row0, int M)
{
#pragma unroll
    for (int i = 0; i < 4; i++) {
        int j = tid + i * 256;
        int r = j >> 4, c = j & 15;
        int g = row0 + r;
        if (g < M) {
            uint4 vh = *(const uint4*)((const char*)Ah + (size_t)r * LDP * 2 + c * 16);
            uint4 vl = *(const uint4*)((const char*)Al + (size_t)r * LDP * 2 + c * 16);
            *(uint4*)((char*)(oh + (size_t)g * CH) + c * 16) = vh;
            float2 a0 = __half22float2(*(__half2*)&vh.x);
            float2 a1 = __half22float2(*(__half2*)&vh.y);
            float2 a2 = __half22float2(*(__half2*)&vh.z);
            float2 a3 = __half22float2(*(__half2*)&vh.w);
            float2 b0 = __half22float2(*(__half2*)&vl.x);
            float2 b1 = __half22float2(*(__half2*)&vl.y);
            float2 b2 = __half22float2(*(__half2*)&vl.z);
            float2 b3 = __half22float2(*(__half2*)&vl.w);
            uint4 sv;
            sv.x = pack_h2_hi(epc * (a0.x + b0.x), epc * (a0.y + b0.y));
            sv.y = pack_h2_hi(epc * (a1.x + b1.x), epc * (a1.y + b1.y));
            sv.z = pack_h2_hi(epc * (a2.x + b2.x), epc * (a2.y + b2.y));
            sv.w = pack_h2_hi(epc * (a3.x + b3.x), epc * (a3.y + b3.y));
            *(uint4*)((char*)(agg + (size_t)g * CH) + c * 16) = sv;
        }
    }
}

// ---------------- encoder GEMM (64-row tile, occ 3): writes h hi plane + agg seed ----------------
#define G1_SMEM (2 * HPLANE_B + PLANE_B + 512)

__global__ __launch_bounds__(256, 3)
void gemm_tc(const float* __restrict__ A, const float4* __restrict__ WhP,
             const float* __restrict__ bias, const float* __restrict__ epsp,
             __half* __restrict__ oh, __half* __restrict__ agg, int M)
{
    extern __shared__ char sm[];
    __half* Ah = (__half*)sm;
    __half* Al = Ah + 64 * LDP;
    __half* Wh = Al + 64 * LDP;
    float* sbias = (float*)(sm + 2 * HPLANE_B + PLANE_B);
    uint32_t sbW = (uint32_t)__cvta_generic_to_shared(Wh);

    const int tid = threadIdx.x;
    const int warp = tid >> 5, lane = tid & 31;
    const int row0 = blockIdx.x * 64;

#pragma unroll
    for (int i = 0; i < 9; i++) {
        int j = tid + i * 256;
        if (j < PLANE_F4) cp16(sbW + j * 16, WhP + j);
    }
    if (tid < 128) sbias[tid] = __ldg(bias + tid);
    const float epc = 1.0f + __ldg(epsp);

    stage_a_f16_64(A, Ah, Al, tid, row0, M);
    cp_commit_wait();
    __syncthreads();

    const int wr0 = (warp >> 1) * 16;
    const int wc0 = (warp & 1) * 64;

    float acc[8][4];
    mma_pass16(Ah, Al, Wh, lane, wr0, wc0, acc);
    __syncthreads();

    z_to_planes16(Ah, Al, sbias, acc, lane, wr0, wc0);
    __syncthreads();
    planes_to_global64_agg(Ah, Al, oh, agg, epc, tid, row0, M);
}

// ---------------- fused 2-layer MLP (64-row tile, occ 3, W reloaded) ----------------
// A input = fp16 agg plane (cp.async staged); layer 1 is 1-term.
#define G2_SMEM (2 * HPLANE_B + PLANE_B + 1024)

template <bool OUT16>
__global__ __launch_bounds__(256, 3)
void gemm2_tc(const __half* __restrict__ A,
              const float4* __restrict__ W1P, const float4* __restrict__ W2P,
              const float* __restrict__ b1, const float* __restrict__ b2,
              const float* __restrict__ epsNext,
              float* __restrict__ out, __half* __restrict__ oh,
              __half* __restrict__ agg, int M)
{
    extern __shared__ char sm[];
    __half* Ah = (__half*)sm;
    __half* Al = Ah + 64 * LDP;
    __half* Wp = Al + 64 * LDP;
    float* sb1 = (float*)(sm + 2 * HPLANE_B + PLANE_B);
    float* sb2 = sb1 + 128;
    uint32_t sbW = (uint32_t)__cvta_generic_to_shared(Wp);
    uint32_t sbA = (uint32_t)__cvta_generic_to_shared(Ah);

    const int tid = threadIdx.x;
    const int warp = tid >> 5, lane = tid & 31;
    const int row0 = blockIdx.x * 64;

#pragma unroll
    for (int i = 0; i < 9; i++) {
        int j = tid + i * 256;
        if (j < PLANE_F4) cp16(sbW + j * 16, W1P + j);
    }
    if (tid < 128) sb1[tid] = __ldg(b1 + tid);
    else           sb2[tid - 128] = __ldg(b2 + tid - 128);
    float epc = 1.0f;
    if (OUT16) epc = 1.0f + __ldg(epsNext);

    // stage A tile (fp16 agg rows) via coalesced cp.async: 64 rows x 256B
#pragma unroll
    for (int i = 0; i < 4; i++) {
        int j = tid + i * 256;
        int r = j >> 4, c = j & 15;
        int g = row0 + r;
        if (g < M)
            cp16(sbA + r * (LDP * 2) + c * 16, (const char*)(A + (size_t)g * CH) + c * 16);
    }
    cp_commit_wait();
    __syncthreads();

    const int wr0 = (warp >> 1) * 16;
    const int wc0 = (warp & 1) * 64;

    // ---- layer 1 (1-term: A is fp16-precision) ----
    float acc[8][4];
    mma_pass16_1t(Ah, Wp, lane, wr0, wc0, acc);
    __syncthreads();

#pragma unroll
    for (int i = 0; i < 9; i++) {
        int j = tid + i * 256;
        if (j < PLANE_F4) cp16(sbW + j * 16, W2P + j);
    }
    z_to_planes16(Ah, Al, sb1, acc, lane, wr0, wc0);
    cp_commit_wait();
    __syncthreads();

    // ---- layer 2 (2-term: z hi/lo) ----
    mma_pass16(Ah, Al, Wp, lane, wr0, wc0, acc);
    __syncthreads();

    if (OUT16) {
        z_to_planes16(Ah, Al, sb2, acc, lane, wr0, wc0);
        __syncthreads();
        planes_to_global64_agg(Ah, Al, oh, agg, epc, tid, row0, M);
    } else {
        float* ftile = (float*)sm;
        const int cb = (lane & 3) * 2;
        const int rl = wr0 + (lane >> 2);
#pragma unroll
        for (int t = 0; t < 8; t++) {
            const int n = wc0 + t * 8 + cb;
            const float b0 = sb2[n], b1v = sb2[n + 1];
            float2 o0 = make_float2(fmaxf(acc[t][0] + b0, 0.f),
                                    fmaxf(acc[t][1] + b1v, 0.f));
            float2 o1 = make_float2(fmaxf(acc[t][2] + b0, 0.f),
                                    fmaxf(acc[t][3] + b1v, 0.f));
            *(float2*)(ftile + (size_t)rl * FT_PITCH + n)       = o0;
            *(float2*)(ftile + (size_t)(rl + 8) * FT_PITCH + n) = o1;
        }
        __syncthreads();
#pragma unroll
        for (int i = 0; i < 8; i++) {
            int j = tid + i * 256;
            int r = j >> 5, c = j & 31;
            int g = row0 + r;
            if (g < M) {
                float4 v = *(const float4*)(ftile + (size_t)r * FT_PITCH + c * 4);
                *(float4*)(out + (size_t)g * CH + c * 4) = v;
            }
        }
    }
}

// ---------------- launch ----------------
extern "C" void kernel_launch(void* const* d_in, const int* in_sizes, int n_in,
                              void* d_out, int out_size)
{
    const float* x     = (const float*)d_in[0];
    const void*  eidx  = d_in[1];
    const float* eattr = (const float*)d_in[2];
    const float* W_enc = (const float*)d_in[3];
    const float* b_enc = (const float*)d_in[4];
    const float* We1   = (const float*)d_in[5];
    const float* be1   = (const float*)d_in[6];
    const float* W11   = (const float*)d_in[7];
    const float* b11   = (const float*)d_in[8];
    const float* W12   = (const float*)d_in[9];
    const float* b12   = (const float*)d_in[10];
    const float* eps1  = (const float*)d_in[11];
    const float* We2   = (const float*)d_in[12];
    const float* be2   = (const float*)d_in[13];
    const float* W21   = (const float*)d_in[14];
    const float* b21   = (const float*)d_in[15];
    const float* W22   = (const float*)d_in[16];
    const float* b22   = (const float*)d_in[17];
    const float* eps2  = (const float*)d_in[18];

    const int N = in_sizes[0] / CH;
    const int E = in_sizes[2] / 16;
    float* out = (float*)d_out;

    float4* wpl;
    __half *hhP, *aggP;
    cudaGetSymbolAddress((void**)&wpl, g_wplanes);
    cudaGetSymbolAddress((void**)&hhP, g_hh);
    cudaGetSymbolAddress((void**)&aggP, g_agg);

    cudaFuncSetAttribute((const void*)gemm_tc,
                         cudaFuncAttributeMaxDynamicSharedMemorySize, G1_SMEM);
    cudaFuncSetAttribute((const void*)gemm2_tc<true>,
                         cudaFuncAttributeMaxDynamicSharedMemorySize, G2_SMEM);
    cudaFuncSetAttribute((const void*)gemm2_tc<false>,
                         cudaFuncAttributeMaxDynamicSharedMemorySize, G2_SMEM);
    cudaFuncSetAttribute((const void*)msggemm_kernel,
                         cudaFuncAttributeMaxDynamicSharedMemorySize, MG_SMEM);

    const int nb = (N + 1023) / 1024;
    const int gb = (N + 63) / 64;
    const int ge = (E + 127) / 128;

    cudaStream_t s2;
    cudaStreamCreateWithFlags(&s2, cudaStreamNonBlocking);
    cudaEvent_t evFork, evJoin;
    cudaEventCreateWithFlags(&evFork, cudaEventDisableTiming);
    cudaEventCreateWithFlags(&evJoin, cudaEventDisableTiming);

    init_kernel<<<nb, 1024>>>((const unsigned*)eidx, 2 * E, N);
    cudaEventRecord(evFork, 0);
    cudaStreamWaitEvent(s2, evFork, 0);

    convert_hist_kernel<<<(E + 255) / 256, 256, 0, s2>>>(eidx, E);
    scan1_kernel<<<nb, 1024, 0, s2>>>(N);
    scan2_kernel<<<1, 256, 0, s2>>>(nb, N, E);
    scan3_kernel<<<nb, 1024, 0, s2>>>(N);
    place_kernel<<<(E + 255) / 256, 256, 0, s2>>>(E);
    eprep_kernel<<<(2 * E + 255) / 256, 256, 0, s2>>>(eattr, E);
    cudaEventRecord(evJoin, s2);

    prep_weights<<<(5 * 128 * LDP + 255) / 256, 256>>>(W_enc, W11, W12, W21, W22);
    gemm_tc<<<gb, 256, G1_SMEM>>>(x, wpl, b_enc, eps1, hhP, aggP, N);

    cudaStreamWaitEvent(0, evJoin, 0);

    // ---- conv1 ----
    msggemm_kernel<<<ge, 256, MG_SMEM>>>(We1, be1, hhP, aggP, E);
    gemm2_tc<true><<<gb, 256, G2_SMEM>>>(aggP, wpl + 1 * PLANE_F4, wpl + 2 * PLANE_F4,
                                         b11, b12, eps2, nullptr, hhP, aggP, N);

    // ---- conv2 ----
    msggemm_kernel<<<ge, 256, MG_SMEM>>>(We2, be2, hhP, aggP, E);
    gemm2_tc<false><<<gb, 256, G2_SMEM>>>(aggP, wpl + 3 * PLANE_F4, wpl + 4 * PLANE_F4,
                                          b21, b22, nullptr, out, nullptr, nullptr, N);
}